// round 13
// baseline (speedup 1.0000x reference)
#include <cuda_runtime.h>
#include <cuda_fp16.h>
#include <cstdint>

// ---------------- problem constants ----------------
#define BB   2
#define SEQ  2048
#define DIM  1024
#define NH   16
#define HD   64
#define BNR  (BB*SEQ)        // 4096
#define QKVC (3*HD)          // 192
#define NQKV (NH*QKVC)       // 3072

// softmax scale folded into q at gemm1 epilogue: 0.125 * log2(e)
#define QSCALE 0.1803368801111204f

// ---------------- device scratch ----------------
__device__ __half g_x    [BNR * DIM];
__device__ __half g_wqkvT[NQKV * DIM];
__device__ __half g_woT  [DIM * DIM];
__device__ __half g_qkv  [BNR * NQKV];
__device__ __half g_sa   [BNR * DIM];
__device__ float  g_o0   [BNR * DIM];    // split-KV partial O (split 0)
__device__ float  g_o1   [BNR * DIM];    // split 1
__device__ float  g_l0   [BNR * NH];     // split-KV partial l
__device__ float  g_l1   [BNR * NH];
__device__ int    g_flag [256];          // per (b,h,qt-8) arrival counter

// split-KV schedule: 24 blocks per (b,h), sorted by cost desc.
__constant__ short c_qt[24] = {7,15,15,14,14,6,13,13,12,12,5,11,11,10,10,4,9,9,8,8,3,2,1,0};
__constant__ short c_k0[24] = {0,0,16,0,15,0,0,14,0,13,0,0,12,0,11,0,0,10,0,9,0,0,0,0};
__constant__ short c_k1[24] = {16,16,32,15,30,14,14,28,13,26,12,12,24,11,22,10,10,20,9,18,8,6,4,2};
__constant__ short c_md[24] = {0,1,2,1,2,0,1,2,1,2,0,1,2,1,2,0,1,2,1,2,0,0,0,0};

// ---------------- helpers ----------------
__device__ __forceinline__ float ex2(float x) {
    float r; asm("ex2.approx.ftz.f32 %0, %1;" : "=f"(r) : "f"(x)); return r;
}
__device__ __forceinline__ uint32_t pack_h2(float hi, float lo) {
    uint32_t d; asm("cvt.rn.f16x2.f32 %0, %1, %2;" : "=r"(d) : "f"(hi), "f"(lo)); return d;
}
__device__ __forceinline__ uint32_t smem_u32(const void* p) {
    uint32_t a;
    asm("{ .reg .u64 t; cvta.to.shared.u64 t, %1; cvt.u32.u64 %0, t; }" : "=r"(a) : "l"(p));
    return a;
}
#define CP16(dst, src) asm volatile("cp.async.cg.shared.global [%0], [%1], 16;" :: "r"(dst), "l"(src) : "memory")
#define CP_COMMIT()    asm volatile("cp.async.commit_group;" ::: "memory")
#define CP_WAIT1()     asm volatile("cp.async.wait_group 1;" ::: "memory")

__device__ __forceinline__ void mma_f16(float& d0, float& d1, float& d2, float& d3,
                                        uint32_t a0, uint32_t a1, uint32_t a2, uint32_t a3,
                                        uint32_t b0, uint32_t b1)
{
    asm volatile("mma.sync.aligned.m16n8k16.row.col.f32.f16.f16.f32 "
                 "{%0,%1,%2,%3}, {%4,%5,%6,%7}, {%8,%9}, {%0,%1,%2,%3};"
                 : "+f"(d0), "+f"(d1), "+f"(d2), "+f"(d3)
                 : "r"(a0), "r"(a1), "r"(a2), "r"(a3), "r"(b0), "r"(b1));
}
__device__ __forceinline__ void ldsm4(uint32_t& r0, uint32_t& r1, uint32_t& r2, uint32_t& r3,
                                      uint32_t addr)
{
    asm volatile("ldmatrix.sync.aligned.m8n8.x4.shared.b16 {%0,%1,%2,%3}, [%4];"
                 : "=r"(r0), "=r"(r1), "=r"(r2), "=r"(r3) : "r"(addr));
}
__device__ __forceinline__ void ldsm4t(uint32_t& r0, uint32_t& r1, uint32_t& r2, uint32_t& r3,
                                       uint32_t addr)
{
    asm volatile("ldmatrix.sync.aligned.m8n8.x4.trans.shared.b16 {%0,%1,%2,%3}, [%4];"
                 : "=r"(r0), "=r"(r1), "=r"(r2), "=r"(r3) : "r"(addr));
}

// ---------------- fused prep: x->half, Wqkv->[n][k], Wo->[n][k], zero flags --------
__global__ void prep_kernel(const float* __restrict__ x,
                            const float* __restrict__ Wqkv,
                            const float* __restrict__ Wo)
{
    __shared__ float t[32][33];
    const int b = blockIdx.x, tid = threadIdx.x;

    if (b < 4096) {
        if (b == 0) g_flag[tid] = 0;
        int i = b * 256 + tid;
        float4 v = ((const float4*)x)[i];
        uint2 o = { pack_h2(v.y, v.x), pack_h2(v.w, v.z) };
        ((uint2*)g_x)[i] = o;
        return;
    }

    const float* inz; __half* outz; int R, C, bx, by;
    if (b < 4096 + 3072) {
        int bb = b - 4096;
        int bxi = bb % 6, byi = (bb / 6) % 32, z = bb / 192;
        R = DIM; C = QKVC; bx = bxi * 32; by = byi * 32;
        inz = Wqkv + (size_t)z * R * C;
        outz = g_wqkvT + (size_t)z * R * C;
    } else {
        int bb = b - 7168;
        int bxi = bb & 31, byi = bb >> 5;
        R = DIM; C = DIM; bx = bxi * 32; by = byi * 32;
        inz = Wo; outz = g_woT;
    }
    const int tx = tid & 31, ty = tid >> 5;
    int xcol = bx + tx;
#pragma unroll
    for (int i = ty; i < 32; i += 8)
        t[i][tx] = inz[(size_t)(by + i) * C + xcol];
    __syncthreads();
    int ox = by + tx;
#pragma unroll
    for (int i = ty; i < 32; i += 8)
        outz[(size_t)(bx + i) * R + ox] = __float2half(t[tx][i]);
}

// ================= fp16 mma GEMM: BK=64, 3-stage cp.async, frag double-buffer =======
#define GEMM_SMEM (3 * 32768)

template<int MODE>   // 0: float out; 1: half out with q-scale (qkv)
__global__ __launch_bounds__(256, 2)
void gemm_h(const __half* __restrict__ A, const __half* __restrict__ Bt,
            const float* __restrict__ bias, void* __restrict__ Cv, int K, int N)
{
    extern __shared__ char smc[];
    const int tid = threadIdx.x, lane = tid & 31, wid = tid >> 5;
    const int warpM = (wid & 3) * 32, warpN = (wid >> 2) * 64;
    const int m0 = blockIdx.y * 128, n0 = blockIdx.x * 128;
    const int gr = lane >> 2, gc = lane & 3;
    const uint32_t sbase = smem_u32(smc);

    const int crow = tid >> 3, cg = tid & 7;
    const uint32_t cdst = (uint32_t)(crow * 128 + ((cg ^ (crow & 7)) << 4));
    const __half* Asrc = A + (size_t)(m0 + crow) * K + cg * 8;
    const __half* Bsrc = Bt + (size_t)(n0 + crow) * K + cg * 8;

    const int a_r = warpM + (lane & 15);
    const uint32_t aX = (uint32_t)(a_r & 7), agsel = (uint32_t)(lane >> 4);
    const int b_r = warpN + ((lane >> 4) << 3) + (lane & 7);
    const uint32_t bX = (uint32_t)(lane & 7), bgsel = (uint32_t)((lane >> 3) & 1);

    float acc[2][8][4];
#pragma unroll
    for (int mi = 0; mi < 2; mi++)
#pragma unroll
        for (int ni = 0; ni < 8; ni++)
#pragma unroll
            for (int q = 0; q < 4; q++) acc[mi][ni][q] = 0.f;

    const int NC = K / 64;

    auto issue = [&](int c, int st) {
        const uint32_t stb = sbase + (uint32_t)(st * 32768);
        const __half* Ap = Asrc + c * 64;
        const __half* Bp = Bsrc + c * 64;
#pragma unroll
        for (int t = 0; t < 4; t++) {
            CP16(stb + cdst + (uint32_t)(t * 4096), Ap + (size_t)t * 32 * K);
            CP16(stb + 16384u + cdst + (uint32_t)(t * 4096), Bp + (size_t)t * 32 * K);
        }
    };

    issue(0, 0); CP_COMMIT();
    issue(1, 1); CP_COMMIT();

    for (int c = 0; c < NC; c++) {
        const int st = c % 3;
        CP_WAIT1();
        __syncthreads();
        if (c + 2 < NC) issue(c + 2, (c + 2) % 3);
        CP_COMMIT();

        const uint32_t stb = sbase + (uint32_t)(st * 32768);
        const uint32_t aBase = stb + (uint32_t)(a_r * 128);
        const uint32_t bBase = stb + 16384u + (uint32_t)(b_r * 128);

        // fragment double buffer across the 4 ks steps
        uint32_t a[2][2][4], b[2][8][2];
        {
            const uint32_t ac = (agsel ^ aX) << 4;
            const uint32_t bc = (bgsel ^ bX) << 4;
            ldsm4(a[0][0][0], a[0][0][1], a[0][0][2], a[0][0][3], aBase + ac);
            ldsm4(a[0][1][0], a[0][1][1], a[0][1][2], a[0][1][3], aBase + 2048u + ac);
#pragma unroll
            for (int p = 0; p < 4; p++)
                ldsm4(b[0][2*p][0], b[0][2*p][1], b[0][2*p+1][0], b[0][2*p+1][1],
                      bBase + (uint32_t)(p * 2048) + bc);
        }
#pragma unroll
        for (int ks = 0; ks < 4; ks++) {
            const int cur = ks & 1, nxt = cur ^ 1;
            if (ks < 3) {
                const uint32_t ac = ((2u * (ks + 1) + agsel) ^ aX) << 4;
                const uint32_t bc = ((2u * (ks + 1) + bgsel) ^ bX) << 4;
                ldsm4(a[nxt][0][0], a[nxt][0][1], a[nxt][0][2], a[nxt][0][3], aBase + ac);
                ldsm4(a[nxt][1][0], a[nxt][1][1], a[nxt][1][2], a[nxt][1][3], aBase + 2048u + ac);
#pragma unroll
                for (int p = 0; p < 4; p++)
                    ldsm4(b[nxt][2*p][0], b[nxt][2*p][1], b[nxt][2*p+1][0], b[nxt][2*p+1][1],
                          bBase + (uint32_t)(p * 2048) + bc);
            }
#pragma unroll
            for (int mi = 0; mi < 2; mi++)
#pragma unroll
                for (int ni = 0; ni < 8; ni++)
                    mma_f16(acc[mi][ni][0], acc[mi][ni][1], acc[mi][ni][2], acc[mi][ni][3],
                            a[cur][mi][0], a[cur][mi][1], a[cur][mi][2], a[cur][mi][3],
                            b[cur][ni][0], b[cur][ni][1]);
        }
    }

#pragma unroll
    for (int mi = 0; mi < 2; mi++) {
        int row = m0 + warpM + mi * 16 + gr;
#pragma unroll
        for (int ni = 0; ni < 8; ni++) {
            int col = n0 + warpN + ni * 8 + gc * 2;
            float2 bsv = *(const float2*)(bias + col);
            float v00 = acc[mi][ni][0] + bsv.x, v01 = acc[mi][ni][1] + bsv.y;
            float v10 = acc[mi][ni][2] + bsv.x, v11 = acc[mi][ni][3] + bsv.y;
            if (MODE == 1) {
                int j = col % QKVC;
                float sc = (j >= 64 && j < 128) ? QSCALE : 1.0f;
                v00 *= sc; v01 *= sc; v10 *= sc; v11 *= sc;
                __half* Ch = (__half*)Cv;
                *(uint32_t*)&Ch[(size_t)row * N + col]       = pack_h2(v01, v00);
                *(uint32_t*)&Ch[(size_t)(row + 8) * N + col] = pack_h2(v11, v10);
            } else {
                float* Cf = (float*)Cv;
                float2 w0 = { v00, v01 }, w1 = { v10, v11 };
                *(float2*)&Cf[(size_t)row * N + col] = w0;
                *(float2*)&Cf[(size_t)(row + 8) * N + col] = w1;
            }
        }
    }
}

// ================= fp16 flash attention: split-KV + fused combine ===================
#define ATTN_SMEM 65536

__global__ __launch_bounds__(128, 3)
void attn_h()
{
    extern __shared__ char smc[];
    __shared__ int s_old;
    const int tid = threadIdx.x, lane = tid & 31, wid = tid >> 5;
    const int idx = blockIdx.x;
    const int qt = c_qt[idx], kt0 = c_k0[idx], kt1 = c_k1[idx], md = c_md[idx];
    const int h = blockIdx.y, b = blockIdx.z;
    const int bn0 = b * SEQ;
    const int colK = h * QKVC, colQ = colK + HD, colV = colK + 2 * HD;
    const int q0 = qt * 128;
    const int gr = lane >> 2, gc = lane & 3;
    const int qrow = wid * 32 + gr;

    const uint32_t sbase = smem_u32(smc);
    const uint32_t uQ = sbase;
    const uint32_t uKV = sbase + 16384u;

    const int crow = tid >> 3, cg = tid & 7;
    const uint32_t cdst = (uint32_t)(crow * 128 + ((cg ^ (crow & 7)) << 4));

    auto issue_kv = [&](int kt, int st) {
        const __half* Kp = g_qkv + (size_t)(bn0 + kt * 64 + crow) * NQKV + colK + cg * 8;
        const __half* Vp = g_qkv + (size_t)(bn0 + kt * 64 + crow) * NQKV + colV + cg * 8;
        const uint32_t stb = uKV + (uint32_t)(st * 16384);
#pragma unroll
        for (int t = 0; t < 4; t++) {
            CP16(stb + cdst + (uint32_t)(t * 2048), Kp + (size_t)t * 16 * NQKV);
            CP16(stb + 8192u + cdst + (uint32_t)(t * 2048), Vp + (size_t)t * 16 * NQKV);
        }
    };

    {
        const __half* Qp = g_qkv + (size_t)(bn0 + q0 + crow) * NQKV + colQ + cg * 8;
#pragma unroll
        for (int t = 0; t < 8; t++)
            CP16(uQ + cdst + (uint32_t)(t * 2048), Qp + (size_t)t * 16 * NQKV);
    }
    issue_kv(kt0, 0); CP_COMMIT();
    issue_kv(kt0 + 1, 1); CP_COMMIT();

    const int qa_r = wid * 32 + (lane & 15);
    const uint32_t qX = (uint32_t)(qa_r & 7), agsel = (uint32_t)(lane >> 4);
    const uint32_t qBase = uQ + (uint32_t)(qa_r * 128);
    const int kb_r = ((lane >> 4) << 3) + (lane & 7);
    const uint32_t kX = (uint32_t)(lane & 7), bgsel = (uint32_t)((lane >> 3) & 1);
    const int v_r = (((lane >> 3) & 1) << 3) + (lane & 7);
    const uint32_t vX = (uint32_t)(lane & 7), vgsel = (uint32_t)(lane >> 4);

    float accO[2][8][4];
#pragma unroll
    for (int mi = 0; mi < 2; mi++)
#pragma unroll
        for (int ni = 0; ni < 8; ni++)
#pragma unroll
            for (int q = 0; q < 4; q++) accO[mi][ni][q] = 0.f;
    float ls[2][2] = { {0.f, 0.f}, {0.f, 0.f} };

    const int lastq = q0 + wid * 32 + 31;

    for (int kt = kt0; kt < kt1; kt++) {
        const int st = (kt - kt0) % 3;
        CP_WAIT1();
        __syncthreads();
        if (kt + 2 < kt1) issue_kv(kt + 2, (kt - kt0 + 2) % 3);
        CP_COMMIT();

        if (kt * 64 > lastq) continue;

        const uint32_t stK = uKV + (uint32_t)(st * 16384);
        const uint32_t stV = stK + 8192u;

        // ---- S = Q @ K^T ----
        float s[2][8][4];
#pragma unroll
        for (int mi = 0; mi < 2; mi++)
#pragma unroll
            for (int ni = 0; ni < 8; ni++)
#pragma unroll
                for (int q = 0; q < 4; q++) s[mi][ni][q] = 0.f;
#pragma unroll
        for (int ks = 0; ks < 4; ks++) {
            const uint32_t ac = ((2u * ks + agsel) ^ qX) << 4;
            const uint32_t bc = ((2u * ks + bgsel) ^ kX) << 4;
            uint32_t a[2][4], bk[8][2];
            ldsm4(a[0][0], a[0][1], a[0][2], a[0][3], qBase + ac);
            ldsm4(a[1][0], a[1][1], a[1][2], a[1][3], qBase + 2048u + ac);
#pragma unroll
            for (int p = 0; p < 4; p++)
                ldsm4(bk[2*p][0], bk[2*p][1], bk[2*p+1][0], bk[2*p+1][1],
                      stK + (uint32_t)((kb_r + p * 16) * 128) + bc);
#pragma unroll
            for (int ni = 0; ni < 8; ni++) {
                mma_f16(s[0][ni][0], s[0][ni][1], s[0][ni][2], s[0][ni][3],
                        a[0][0], a[0][1], a[0][2], a[0][3], bk[ni][0], bk[ni][1]);
                mma_f16(s[1][ni][0], s[1][ni][1], s[1][ni][2], s[1][ni][3],
                        a[1][0], a[1][1], a[1][2], a[1][3], bk[ni][0], bk[ni][1]);
            }
        }

        // ---- causal mask ----
        if (kt >= 2 * qt) {
            const int kb = kt * 64;
#pragma unroll
            for (int mi = 0; mi < 2; mi++) {
                const int qg = q0 + qrow + mi * 16;
#pragma unroll
                for (int ni = 0; ni < 8; ni++) {
                    int kc = kb + ni * 8 + gc * 2;
                    if (kc     > qg    ) s[mi][ni][0] = -1e30f;
                    if (kc + 1 > qg    ) s[mi][ni][1] = -1e30f;
                    if (kc     > qg + 8) s[mi][ni][2] = -1e30f;
                    if (kc + 1 > qg + 8) s[mi][ni][3] = -1e30f;
                }
            }
        }

        // ---- P = exp2(s); row sums ----
#pragma unroll
        for (int mi = 0; mi < 2; mi++)
#pragma unroll
            for (int ni = 0; ni < 8; ni++) {
                float p0 = ex2(s[mi][ni][0]);
                float p1 = ex2(s[mi][ni][1]);
                float p2 = ex2(s[mi][ni][2]);
                float p3 = ex2(s[mi][ni][3]);
                ls[mi][0] += p0 + p1; ls[mi][1] += p2 + p3;
                s[mi][ni][0] = p0; s[mi][ni][1] = p1;
                s[mi][ni][2] = p2; s[mi][ni][3] = p3;
            }

        // ---- pack P to fp16 A-frags ----
        uint32_t pa[2][4][4];
#pragma unroll
        for (int mi = 0; mi < 2; mi++)
#pragma unroll
            for (int ks = 0; ks < 4; ks++) {
                pa[mi][ks][0] = pack_h2(s[mi][2*ks][1],   s[mi][2*ks][0]);
                pa[mi][ks][1] = pack_h2(s[mi][2*ks][3],   s[mi][2*ks][2]);
                pa[mi][ks][2] = pack_h2(s[mi][2*ks+1][1], s[mi][2*ks+1][0]);
                pa[mi][ks][3] = pack_h2(s[mi][2*ks+1][3], s[mi][2*ks+1][2]);
            }

        // ---- O += P @ V ----
#pragma unroll
        for (int ks = 0; ks < 4; ks++) {
            uint32_t bv[8][2];
#pragma unroll
            for (int p = 0; p < 4; p++) {
                const uint32_t vc = ((2u * p + vgsel) ^ vX) << 4;
                ldsm4t(bv[2*p][0], bv[2*p][1], bv[2*p+1][0], bv[2*p+1][1],
                       stV + (uint32_t)((v_r + ks * 16) * 128) + vc);
            }
#pragma unroll
            for (int ni = 0; ni < 8; ni++) {
                mma_f16(accO[0][ni][0], accO[0][ni][1], accO[0][ni][2], accO[0][ni][3],
                        pa[0][ks][0], pa[0][ks][1], pa[0][ks][2], pa[0][ks][3],
                        bv[ni][0], bv[ni][1]);
                mma_f16(accO[1][ni][0], accO[1][ni][1], accO[1][ni][2], accO[1][ni][3],
                        pa[1][ks][0], pa[1][ks][1], pa[1][ks][2], pa[1][ks][3],
                        bv[ni][0], bv[ni][1]);
            }
        }
    }

    // ---- epilogue ----
#pragma unroll
    for (int mi = 0; mi < 2; mi++) {
        ls[mi][0] += __shfl_xor_sync(0xffffffffu, ls[mi][0], 1);
        ls[mi][0] += __shfl_xor_sync(0xffffffffu, ls[mi][0], 2);
        ls[mi][1] += __shfl_xor_sync(0xffffffffu, ls[mi][1], 1);
        ls[mi][1] += __shfl_xor_sync(0xffffffffu, ls[mi][1], 2);
    }
    if (md == 0) {
#pragma unroll
        for (int mi = 0; mi < 2; mi++) {
            float inv0 = 1.f / ls[mi][0], inv1 = 1.f / ls[mi][1];
            int row = bn0 + q0 + qrow + mi * 16;
#pragma unroll
            for (int ni = 0; ni < 8; ni++) {
                int col = h * HD + ni * 8 + gc * 2;
                *(uint32_t*)&g_sa[(size_t)row * DIM + col] =
                    pack_h2(accO[mi][ni][1] * inv0, accO[mi][ni][0] * inv0);
                *(uint32_t*)&g_sa[(size_t)(row + 8) * DIM + col] =
                    pack_h2(accO[mi][ni][3] * inv1, accO[mi][ni][2] * inv1);
            }
        }
    } else {
        // write own partial
        float* Po = (md == 1) ? g_o0 : g_o1;
        float* Pl = (md == 1) ? g_l0 : g_l1;
#pragma unroll
        for (int mi = 0; mi < 2; mi++) {
            int row = bn0 + q0 + qrow + mi * 16;
            if (gc == 0) {
                Pl[(size_t)row * NH + h]       = ls[mi][0];
                Pl[(size_t)(row + 8) * NH + h] = ls[mi][1];
            }
#pragma unroll
            for (int ni = 0; ni < 8; ni++) {
                int col = h * HD + ni * 8 + gc * 2;
                float2 w0 = { accO[mi][ni][0], accO[mi][ni][1] };
                float2 w1 = { accO[mi][ni][2], accO[mi][ni][3] };
                *(float2*)&Po[(size_t)row * DIM + col] = w0;
                *(float2*)&Po[(size_t)(row + 8) * DIM + col] = w1;
            }
        }
        // arrival protocol: second arriver combines (addition commutative -> deterministic)
        __syncthreads();
        if (tid == 0) {
            __threadfence();
            s_old = atomicAdd(&g_flag[((b * NH + h) << 3) + (qt - 8)], 1);
        }
        __syncthreads();
        if (s_old == 1) {
            __threadfence();
            const float* Qo = (md == 1) ? g_o1 : g_o0;
            const float* Ql = (md == 1) ? g_l1 : g_l0;
#pragma unroll
            for (int mi = 0; mi < 2; mi++) {
                int row = bn0 + q0 + qrow + mi * 16;
                float inv0 = 1.f / (ls[mi][0] + Ql[(size_t)row * NH + h]);
                float inv1 = 1.f / (ls[mi][1] + Ql[(size_t)(row + 8) * NH + h]);
#pragma unroll
                for (int ni = 0; ni < 8; ni++) {
                    int col = h * HD + ni * 8 + gc * 2;
                    float2 o0 = *(const float2*)&Qo[(size_t)row * DIM + col];
                    float2 o1 = *(const float2*)&Qo[(size_t)(row + 8) * DIM + col];
                    *(uint32_t*)&g_sa[(size_t)row * DIM + col] =
                        pack_h2((accO[mi][ni][1] + o0.y) * inv0,
                                (accO[mi][ni][0] + o0.x) * inv0);
                    *(uint32_t*)&g_sa[(size_t)(row + 8) * DIM + col] =
                        pack_h2((accO[mi][ni][3] + o1.y) * inv1,
                                (accO[mi][ni][2] + o1.x) * inv1);
                }
            }
        }
    }
}

// ---------------- launch ----------------
extern "C" void kernel_launch(void* const* d_in, const int* in_sizes, int n_in,
                              void* d_out, int out_size)
{
    const float* x    = (const float*)d_in[0];
    const float* Wqkv = (const float*)d_in[1];
    const float* bqkv = (const float*)d_in[2];
    const float* Wo   = (const float*)d_in[3];
    const float* bo   = (const float*)d_in[4];
    float* out = (float*)d_out;

    __half *xh, *wqkvT, *woT, *qkv, *sa;
    cudaGetSymbolAddress((void**)&xh,    g_x);
    cudaGetSymbolAddress((void**)&wqkvT, g_wqkvT);
    cudaGetSymbolAddress((void**)&woT,   g_woT);
    cudaGetSymbolAddress((void**)&qkv,   g_qkv);
    cudaGetSymbolAddress((void**)&sa,    g_sa);

    cudaFuncSetAttribute(gemm_h<1>, cudaFuncAttributeMaxDynamicSharedMemorySize, GEMM_SMEM);
    cudaFuncSetAttribute(gemm_h<0>, cudaFuncAttributeMaxDynamicSharedMemorySize, GEMM_SMEM);
    cudaFuncSetAttribute(attn_h, cudaFuncAttributeMaxDynamicSharedMemorySize, ATTN_SMEM);

    prep_kernel<<<8192, 256>>>(x, Wqkv, Wo);
    gemm_h<1><<<dim3(NQKV / 128, BNR / 128), 256, GEMM_SMEM>>>(xh, wqkvT, bqkv, qkv, DIM, NQKV);
    attn_h<<<dim3(24, NH, BB), 128, ATTN_SMEM>>>();
    gemm_h<0><<<dim3(DIM / 128, BNR / 128), 256, GEMM_SMEM>>>(sa, woT, bo, out, DIM, DIM);
}

// round 14
// speedup vs baseline: 1.0591x; 1.0591x over previous
#include <cuda_runtime.h>
#include <cuda_fp16.h>
#include <cstdint>

// ---------------- problem constants ----------------
#define BB   2
#define SEQ  2048
#define DIM  1024
#define NH   16
#define HD   64
#define BNR  (BB*SEQ)        // 4096
#define QKVC (3*HD)          // 192
#define NQKV (NH*QKVC)       // 3072

// softmax scale folded into q at gemm1 epilogue: 0.125 * log2(e)
#define QSCALE 0.1803368801111204f

// ---------------- device scratch ----------------
__device__ __half g_x    [BNR * DIM];
__device__ __half g_wqkvT[NQKV * DIM];
__device__ __half g_woT  [DIM * DIM];
__device__ __half g_qkv  [BNR * NQKV];
__device__ __half g_sa   [BNR * DIM];
__device__ float  g_o0   [BNR * DIM];    // split-KV partial O (split 0)
__device__ float  g_o1   [BNR * DIM];    // split 1
__device__ float  g_l0   [BNR * NH];     // split-KV partial l
__device__ float  g_l1   [BNR * NH];

// split-KV schedule: 24 blocks per (b,h), sorted by cost desc.
__constant__ short c_qt[24] = {7,15,15,14,14,6,13,13,12,12,5,11,11,10,10,4,9,9,8,8,3,2,1,0};
__constant__ short c_k0[24] = {0,0,16,0,15,0,0,14,0,13,0,0,12,0,11,0,0,10,0,9,0,0,0,0};
__constant__ short c_k1[24] = {16,16,32,15,30,14,14,28,13,26,12,12,24,11,22,10,10,20,9,18,8,6,4,2};
__constant__ short c_md[24] = {0,1,2,1,2,0,1,2,1,2,0,1,2,1,2,0,1,2,1,2,0,0,0,0};

// ---------------- helpers ----------------
__device__ __forceinline__ uint32_t pack_h2(float hi, float lo) {
    uint32_t d; asm("cvt.rn.f16x2.f32 %0, %1, %2;" : "=r"(d) : "f"(hi), "f"(lo)); return d;
}
__device__ __forceinline__ uint32_t ex2_h2(uint32_t x) {
    uint32_t r; asm("ex2.approx.f16x2 %0, %1;" : "=r"(r) : "r"(x)); return r;
}
__device__ __forceinline__ uint32_t hadd2u(uint32_t a, uint32_t b) {
    uint32_t r; asm("add.f16x2 %0, %1, %2;" : "=r"(r) : "r"(a), "r"(b)); return r;
}
__device__ __forceinline__ uint32_t smem_u32(const void* p) {
    uint32_t a;
    asm("{ .reg .u64 t; cvta.to.shared.u64 t, %1; cvt.u32.u64 %0, t; }" : "=r"(a) : "l"(p));
    return a;
}
#define CP16(dst, src) asm volatile("cp.async.cg.shared.global [%0], [%1], 16;" :: "r"(dst), "l"(src) : "memory")
#define CP_COMMIT()    asm volatile("cp.async.commit_group;" ::: "memory")
#define CP_WAIT1()     asm volatile("cp.async.wait_group 1;" ::: "memory")

__device__ __forceinline__ void mma_f16(float& d0, float& d1, float& d2, float& d3,
                                        uint32_t a0, uint32_t a1, uint32_t a2, uint32_t a3,
                                        uint32_t b0, uint32_t b1)
{
    asm volatile("mma.sync.aligned.m16n8k16.row.col.f32.f16.f16.f32 "
                 "{%0,%1,%2,%3}, {%4,%5,%6,%7}, {%8,%9}, {%0,%1,%2,%3};"
                 : "+f"(d0), "+f"(d1), "+f"(d2), "+f"(d3)
                 : "r"(a0), "r"(a1), "r"(a2), "r"(a3), "r"(b0), "r"(b1));
}
__device__ __forceinline__ void ldsm4(uint32_t& r0, uint32_t& r1, uint32_t& r2, uint32_t& r3,
                                      uint32_t addr)
{
    asm volatile("ldmatrix.sync.aligned.m8n8.x4.shared.b16 {%0,%1,%2,%3}, [%4];"
                 : "=r"(r0), "=r"(r1), "=r"(r2), "=r"(r3) : "r"(addr));
}
__device__ __forceinline__ void ldsm4t(uint32_t& r0, uint32_t& r1, uint32_t& r2, uint32_t& r3,
                                       uint32_t addr)
{
    asm volatile("ldmatrix.sync.aligned.m8n8.x4.trans.shared.b16 {%0,%1,%2,%3}, [%4];"
                 : "=r"(r0), "=r"(r1), "=r"(r2), "=r"(r3) : "r"(addr));
}

// ---------------- fused prep: x->half, Wqkv->[n][k] half, Wo->[n][k] half ----------
__global__ void prep_kernel(const float* __restrict__ x,
                            const float* __restrict__ Wqkv,
                            const float* __restrict__ Wo)
{
    __shared__ float t[32][33];
    const int b = blockIdx.x, tid = threadIdx.x;

    if (b < 4096) {
        int i = b * 256 + tid;
        float4 v = ((const float4*)x)[i];
        uint2 o = { pack_h2(v.y, v.x), pack_h2(v.w, v.z) };
        ((uint2*)g_x)[i] = o;
        return;
    }

    const float* inz; __half* outz; int R, C, bx, by;
    if (b < 4096 + 3072) {
        int bb = b - 4096;
        int bxi = bb % 6, byi = (bb / 6) % 32, z = bb / 192;
        R = DIM; C = QKVC; bx = bxi * 32; by = byi * 32;
        inz = Wqkv + (size_t)z * R * C;
        outz = g_wqkvT + (size_t)z * R * C;
    } else {
        int bb = b - 7168;
        int bxi = bb & 31, byi = bb >> 5;
        R = DIM; C = DIM; bx = bxi * 32; by = byi * 32;
        inz = Wo; outz = g_woT;
    }
    const int tx = tid & 31, ty = tid >> 5;
    int xcol = bx + tx;
#pragma unroll
    for (int i = ty; i < 32; i += 8)
        t[i][tx] = inz[(size_t)(by + i) * C + xcol];
    __syncthreads();
    int ox = by + tx;
#pragma unroll
    for (int i = ty; i < 32; i += 8)
        outz[(size_t)(bx + i) * R + ox] = __float2half(t[tx][i]);
}

// ================= fp16 mma GEMM: BK=64, 3-stage cp.async, 128B-row swizzle ==========
#define GEMM_SMEM (3 * 32768)

template<int MODE>   // 0: float out; 1: half out with q-scale (qkv)
__global__ __launch_bounds__(256, 2)
void gemm_h(const __half* __restrict__ A, const __half* __restrict__ Bt,
            const float* __restrict__ bias, void* __restrict__ Cv, int K, int N)
{
    extern __shared__ char smc[];
    const int tid = threadIdx.x, lane = tid & 31, wid = tid >> 5;
    const int warpM = (wid & 3) * 32, warpN = (wid >> 2) * 64;
    const int m0 = blockIdx.y * 128, n0 = blockIdx.x * 128;
    const int gr = lane >> 2, gc = lane & 3;
    const uint32_t sbase = smem_u32(smc);

    const int crow = tid >> 3, cg = tid & 7;
    const uint32_t cdst = (uint32_t)(crow * 128 + ((cg ^ (crow & 7)) << 4));
    const __half* Asrc = A + (size_t)(m0 + crow) * K + cg * 8;
    const __half* Bsrc = Bt + (size_t)(n0 + crow) * K + cg * 8;

    const int a_r = warpM + (lane & 15);
    const uint32_t aX = (uint32_t)(a_r & 7), agsel = (uint32_t)(lane >> 4);
    const int b_r = warpN + ((lane >> 4) << 3) + (lane & 7);
    const uint32_t bX = (uint32_t)(lane & 7), bgsel = (uint32_t)((lane >> 3) & 1);

    float acc[2][8][4];
#pragma unroll
    for (int mi = 0; mi < 2; mi++)
#pragma unroll
        for (int ni = 0; ni < 8; ni++)
#pragma unroll
            for (int q = 0; q < 4; q++) acc[mi][ni][q] = 0.f;

    const int NC = K / 64;

    auto issue = [&](int c, int st) {
        const uint32_t stb = sbase + (uint32_t)(st * 32768);
        const __half* Ap = Asrc + c * 64;
        const __half* Bp = Bsrc + c * 64;
#pragma unroll
        for (int t = 0; t < 4; t++) {
            CP16(stb + cdst + (uint32_t)(t * 4096), Ap + (size_t)t * 32 * K);
            CP16(stb + 16384u + cdst + (uint32_t)(t * 4096), Bp + (size_t)t * 32 * K);
        }
    };

    issue(0, 0); CP_COMMIT();
    issue(1, 1); CP_COMMIT();

    for (int c = 0; c < NC; c++) {
        const int st = c % 3;
        CP_WAIT1();
        __syncthreads();
        if (c + 2 < NC) issue(c + 2, (c + 2) % 3);
        CP_COMMIT();

        const uint32_t stb = sbase + (uint32_t)(st * 32768);
        const uint32_t aBase = stb + (uint32_t)(a_r * 128);
        const uint32_t bBase = stb + 16384u + (uint32_t)(b_r * 128);
#pragma unroll
        for (int ks = 0; ks < 4; ks++) {
            const uint32_t ac = ((2u * ks + agsel) ^ aX) << 4;
            const uint32_t bc = ((2u * ks + bgsel) ^ bX) << 4;
            uint32_t a[2][4], b[8][2];
            ldsm4(a[0][0], a[0][1], a[0][2], a[0][3], aBase + ac);
            ldsm4(a[1][0], a[1][1], a[1][2], a[1][3], aBase + 2048u + ac);
#pragma unroll
            for (int p = 0; p < 4; p++)
                ldsm4(b[2*p][0], b[2*p][1], b[2*p+1][0], b[2*p+1][1],
                      bBase + (uint32_t)(p * 2048) + bc);
#pragma unroll
            for (int mi = 0; mi < 2; mi++)
#pragma unroll
                for (int ni = 0; ni < 8; ni++)
                    mma_f16(acc[mi][ni][0], acc[mi][ni][1], acc[mi][ni][2], acc[mi][ni][3],
                            a[mi][0], a[mi][1], a[mi][2], a[mi][3], b[ni][0], b[ni][1]);
        }
    }

#pragma unroll
    for (int mi = 0; mi < 2; mi++) {
        int row = m0 + warpM + mi * 16 + gr;
#pragma unroll
        for (int ni = 0; ni < 8; ni++) {
            int col = n0 + warpN + ni * 8 + gc * 2;
            float2 bsv = *(const float2*)(bias + col);
            float v00 = acc[mi][ni][0] + bsv.x, v01 = acc[mi][ni][1] + bsv.y;
            float v10 = acc[mi][ni][2] + bsv.x, v11 = acc[mi][ni][3] + bsv.y;
            if (MODE == 1) {
                int j = col % QKVC;
                float sc = (j >= 64 && j < 128) ? QSCALE : 1.0f;
                v00 *= sc; v01 *= sc; v10 *= sc; v11 *= sc;
                __half* Ch = (__half*)Cv;
                *(uint32_t*)&Ch[(size_t)row * N + col]       = pack_h2(v01, v00);
                *(uint32_t*)&Ch[(size_t)(row + 8) * N + col] = pack_h2(v11, v10);
            } else {
                float* Cf = (float*)Cv;
                float2 w0 = { v00, v01 }, w1 = { v10, v11 };
                *(float2*)&Cf[(size_t)row * N + col] = w0;
                *(float2*)&Cf[(size_t)(row + 8) * N + col] = w1;
            }
        }
    }
}

// ================= fp16 flash attention: split-KV, h2 exp, 3 CTA/SM =================
#define ATTN_SMEM 65536

__global__ __launch_bounds__(128, 3)
void attn_h()
{
    extern __shared__ char smc[];
    const int tid = threadIdx.x, lane = tid & 31, wid = tid >> 5;
    const int idx = blockIdx.x;
    const int qt = c_qt[idx], kt0 = c_k0[idx], kt1 = c_k1[idx], md = c_md[idx];
    const int h = blockIdx.y, b = blockIdx.z;
    const int bn0 = b * SEQ;
    const int colK = h * QKVC, colQ = colK + HD, colV = colK + 2 * HD;
    const int q0 = qt * 128;
    const int gr = lane >> 2, gc = lane & 3;
    const int qrow = wid * 32 + gr;

    const uint32_t sbase = smem_u32(smc);
    const uint32_t uQ = sbase;
    const uint32_t uKV = sbase + 16384u;

    const int crow = tid >> 3, cg = tid & 7;
    const uint32_t cdst = (uint32_t)(crow * 128 + ((cg ^ (crow & 7)) << 4));

    auto issue_kv = [&](int kt, int st) {
        const __half* Kp = g_qkv + (size_t)(bn0 + kt * 64 + crow) * NQKV + colK + cg * 8;
        const __half* Vp = g_qkv + (size_t)(bn0 + kt * 64 + crow) * NQKV + colV + cg * 8;
        const uint32_t stb = uKV + (uint32_t)(st * 16384);
#pragma unroll
        for (int t = 0; t < 4; t++) {
            CP16(stb + cdst + (uint32_t)(t * 2048), Kp + (size_t)t * 16 * NQKV);
            CP16(stb + 8192u + cdst + (uint32_t)(t * 2048), Vp + (size_t)t * 16 * NQKV);
        }
    };

    {
        const __half* Qp = g_qkv + (size_t)(bn0 + q0 + crow) * NQKV + colQ + cg * 8;
#pragma unroll
        for (int t = 0; t < 8; t++)
            CP16(uQ + cdst + (uint32_t)(t * 2048), Qp + (size_t)t * 16 * NQKV);
    }
    issue_kv(kt0, 0); CP_COMMIT();
    issue_kv(kt0 + 1, 1); CP_COMMIT();

    const int qa_r = wid * 32 + (lane & 15);
    const uint32_t qX = (uint32_t)(qa_r & 7), agsel = (uint32_t)(lane >> 4);
    const uint32_t qBase = uQ + (uint32_t)(qa_r * 128);
    const int kb_r = ((lane >> 4) << 3) + (lane & 7);
    const uint32_t kX = (uint32_t)(lane & 7), bgsel = (uint32_t)((lane >> 3) & 1);
    const int v_r = (((lane >> 3) & 1) << 3) + (lane & 7);
    const uint32_t vX = (uint32_t)(lane & 7), vgsel = (uint32_t)(lane >> 4);

    float accO[2][8][4];
#pragma unroll
    for (int mi = 0; mi < 2; mi++)
#pragma unroll
        for (int ni = 0; ni < 8; ni++)
#pragma unroll
            for (int q = 0; q < 4; q++) accO[mi][ni][q] = 0.f;
    float ls[2][2] = { {0.f, 0.f}, {0.f, 0.f} };

    const int lastq = q0 + wid * 32 + 31;

    for (int kt = kt0; kt < kt1; kt++) {
        const int st = (kt - kt0) % 3;
        CP_WAIT1();
        __syncthreads();
        if (kt + 2 < kt1) issue_kv(kt + 2, (kt - kt0 + 2) % 3);
        CP_COMMIT();

        if (kt * 64 > lastq) continue;

        const uint32_t stK = uKV + (uint32_t)(st * 16384);
        const uint32_t stV = stK + 8192u;

        // ---- S = Q @ K^T ----
        float s[2][8][4];
#pragma unroll
        for (int mi = 0; mi < 2; mi++)
#pragma unroll
            for (int ni = 0; ni < 8; ni++)
#pragma unroll
                for (int q = 0; q < 4; q++) s[mi][ni][q] = 0.f;
#pragma unroll
        for (int ks = 0; ks < 4; ks++) {
            const uint32_t ac = ((2u * ks + agsel) ^ qX) << 4;
            const uint32_t bc = ((2u * ks + bgsel) ^ kX) << 4;
            uint32_t a[2][4], bk[8][2];
            ldsm4(a[0][0], a[0][1], a[0][2], a[0][3], qBase + ac);
            ldsm4(a[1][0], a[1][1], a[1][2], a[1][3], qBase + 2048u + ac);
#pragma unroll
            for (int p = 0; p < 4; p++)
                ldsm4(bk[2*p][0], bk[2*p][1], bk[2*p+1][0], bk[2*p+1][1],
                      stK + (uint32_t)((kb_r + p * 16) * 128) + bc);
#pragma unroll
            for (int ni = 0; ni < 8; ni++) {
                mma_f16(s[0][ni][0], s[0][ni][1], s[0][ni][2], s[0][ni][3],
                        a[0][0], a[0][1], a[0][2], a[0][3], bk[ni][0], bk[ni][1]);
                mma_f16(s[1][ni][0], s[1][ni][1], s[1][ni][2], s[1][ni][3],
                        a[1][0], a[1][1], a[1][2], a[1][3], bk[ni][0], bk[ni][1]);
            }
        }

        // ---- causal mask ----
        if (kt >= 2 * qt) {
            const int kb = kt * 64;
#pragma unroll
            for (int mi = 0; mi < 2; mi++) {
                const int qg = q0 + qrow + mi * 16;
#pragma unroll
                for (int ni = 0; ni < 8; ni++) {
                    int kc = kb + ni * 8 + gc * 2;
                    if (kc     > qg    ) s[mi][ni][0] = -1e30f;
                    if (kc + 1 > qg    ) s[mi][ni][1] = -1e30f;
                    if (kc     > qg + 8) s[mi][ni][2] = -1e30f;
                    if (kc + 1 > qg + 8) s[mi][ni][3] = -1e30f;
                }
            }
        }

        // ---- pack s to h2, then P = ex2.f16x2 (half the MUFU ops) ----
        uint32_t pa[2][4][4];
#pragma unroll
        for (int mi = 0; mi < 2; mi++)
#pragma unroll
            for (int ks = 0; ks < 4; ks++) {
                pa[mi][ks][0] = ex2_h2(pack_h2(s[mi][2*ks][1],   s[mi][2*ks][0]));
                pa[mi][ks][1] = ex2_h2(pack_h2(s[mi][2*ks][3],   s[mi][2*ks][2]));
                pa[mi][ks][2] = ex2_h2(pack_h2(s[mi][2*ks+1][1], s[mi][2*ks+1][0]));
                pa[mi][ks][3] = ex2_h2(pack_h2(s[mi][2*ks+1][3], s[mi][2*ks+1][2]));
            }

        // ---- tile-local row sums in h2, folded into fp32 ----
#pragma unroll
        for (int mi = 0; mi < 2; mi++) {
            uint32_t h0 = hadd2u(hadd2u(pa[mi][0][0], pa[mi][0][2]),
                                 hadd2u(pa[mi][1][0], pa[mi][1][2]));
            uint32_t h0b = hadd2u(hadd2u(pa[mi][2][0], pa[mi][2][2]),
                                  hadd2u(pa[mi][3][0], pa[mi][3][2]));
            uint32_t h1 = hadd2u(hadd2u(pa[mi][0][1], pa[mi][0][3]),
                                 hadd2u(pa[mi][1][1], pa[mi][1][3]));
            uint32_t h1b = hadd2u(hadd2u(pa[mi][2][1], pa[mi][2][3]),
                                  hadd2u(pa[mi][3][1], pa[mi][3][3]));
            float2 f0 = __half22float2(*(const __half2*)&h0);
            float2 f0b = __half22float2(*(const __half2*)&h0b);
            float2 f1 = __half22float2(*(const __half2*)&h1);
            float2 f1b = __half22float2(*(const __half2*)&h1b);
            ls[mi][0] += (f0.x + f0.y) + (f0b.x + f0b.y);
            ls[mi][1] += (f1.x + f1.y) + (f1b.x + f1b.y);
        }

        // ---- O += P @ V ----
#pragma unroll
        for (int ks = 0; ks < 4; ks++) {
            uint32_t bv[8][2];
#pragma unroll
            for (int p = 0; p < 4; p++) {
                const uint32_t vc = ((2u * p + vgsel) ^ vX) << 4;
                ldsm4t(bv[2*p][0], bv[2*p][1], bv[2*p+1][0], bv[2*p+1][1],
                       stV + (uint32_t)((v_r + ks * 16) * 128) + vc);
            }
#pragma unroll
            for (int ni = 0; ni < 8; ni++) {
                mma_f16(accO[0][ni][0], accO[0][ni][1], accO[0][ni][2], accO[0][ni][3],
                        pa[0][ks][0], pa[0][ks][1], pa[0][ks][2], pa[0][ks][3],
                        bv[ni][0], bv[ni][1]);
                mma_f16(accO[1][ni][0], accO[1][ni][1], accO[1][ni][2], accO[1][ni][3],
                        pa[1][ks][0], pa[1][ks][1], pa[1][ks][2], pa[1][ks][3],
                        bv[ni][0], bv[ni][1]);
            }
        }
    }

    // ---- epilogue ----
#pragma unroll
    for (int mi = 0; mi < 2; mi++) {
        ls[mi][0] += __shfl_xor_sync(0xffffffffu, ls[mi][0], 1);
        ls[mi][0] += __shfl_xor_sync(0xffffffffu, ls[mi][0], 2);
        ls[mi][1] += __shfl_xor_sync(0xffffffffu, ls[mi][1], 1);
        ls[mi][1] += __shfl_xor_sync(0xffffffffu, ls[mi][1], 2);
    }
    if (md == 0) {
#pragma unroll
        for (int mi = 0; mi < 2; mi++) {
            float inv0 = 1.f / ls[mi][0], inv1 = 1.f / ls[mi][1];
            int row = bn0 + q0 + qrow + mi * 16;
#pragma unroll
            for (int ni = 0; ni < 8; ni++) {
                int col = h * HD + ni * 8 + gc * 2;
                *(uint32_t*)&g_sa[(size_t)row * DIM + col] =
                    pack_h2(accO[mi][ni][1] * inv0, accO[mi][ni][0] * inv0);
                *(uint32_t*)&g_sa[(size_t)(row + 8) * DIM + col] =
                    pack_h2(accO[mi][ni][3] * inv1, accO[mi][ni][2] * inv1);
            }
        }
    } else {
        float* Po = (md == 1) ? g_o0 : g_o1;
        float* Pl = (md == 1) ? g_l0 : g_l1;
#pragma unroll
        for (int mi = 0; mi < 2; mi++) {
            int row = bn0 + q0 + qrow + mi * 16;
            if (gc == 0) {
                Pl[(size_t)row * NH + h]       = ls[mi][0];
                Pl[(size_t)(row + 8) * NH + h] = ls[mi][1];
            }
#pragma unroll
            for (int ni = 0; ni < 8; ni++) {
                int col = h * HD + ni * 8 + gc * 2;
                float2 w0 = { accO[mi][ni][0], accO[mi][ni][1] };
                float2 w1 = { accO[mi][ni][2], accO[mi][ni][3] };
                *(float2*)&Po[(size_t)row * DIM + col] = w0;
                *(float2*)&Po[(size_t)(row + 8) * DIM + col] = w1;
            }
        }
    }
}

// ---------------- split-KV combine: rows with qt>=8 (local rows 1024..2047) --------
__global__ void combine_kernel()
{
    int b = blockIdx.x >> 10;
    int rl = 1024 + (blockIdx.x & 1023);
    size_t row = (size_t)b * SEQ + rl;
    int col = threadIdx.x * 4;
    int h = col >> 6;
    float inv = 1.f / (g_l0[row * NH + h] + g_l1[row * NH + h]);
    float4 a = *(const float4*)&g_o0[row * DIM + col];
    float4 c = *(const float4*)&g_o1[row * DIM + col];
    uint2 o = { pack_h2((a.y + c.y) * inv, (a.x + c.x) * inv),
                pack_h2((a.w + c.w) * inv, (a.z + c.z) * inv) };
    *(uint2*)&g_sa[row * DIM + col] = o;
}

// ---------------- launch ----------------
extern "C" void kernel_launch(void* const* d_in, const int* in_sizes, int n_in,
                              void* d_out, int out_size)
{
    const float* x    = (const float*)d_in[0];
    const float* Wqkv = (const float*)d_in[1];
    const float* bqkv = (const float*)d_in[2];
    const float* Wo   = (const float*)d_in[3];
    const float* bo   = (const float*)d_in[4];
    float* out = (float*)d_out;

    __half *xh, *wqkvT, *woT, *qkv, *sa;
    cudaGetSymbolAddress((void**)&xh,    g_x);
    cudaGetSymbolAddress((void**)&wqkvT, g_wqkvT);
    cudaGetSymbolAddress((void**)&woT,   g_woT);
    cudaGetSymbolAddress((void**)&qkv,   g_qkv);
    cudaGetSymbolAddress((void**)&sa,    g_sa);

    cudaFuncSetAttribute(gemm_h<1>, cudaFuncAttributeMaxDynamicSharedMemorySize, GEMM_SMEM);
    cudaFuncSetAttribute(gemm_h<0>, cudaFuncAttributeMaxDynamicSharedMemorySize, GEMM_SMEM);
    cudaFuncSetAttribute(attn_h, cudaFuncAttributeMaxDynamicSharedMemorySize, ATTN_SMEM);

    prep_kernel<<<8192, 256>>>(x, Wqkv, Wo);
    gemm_h<1><<<dim3(NQKV / 128, BNR / 128), 256, GEMM_SMEM>>>(xh, wqkvT, bqkv, qkv, DIM, NQKV);
    attn_h<<<dim3(24, NH, BB), 128, ATTN_SMEM>>>();
    combine_kernel<<<2048, 256>>>();
    gemm_h<0><<<dim3(DIM / 128, BNR / 128), 256, GEMM_SMEM>>>(sa, woT, bo, out, DIM, DIM);
}

// round 15
// speedup vs baseline: 1.0675x; 1.0079x over previous
#include <cuda_runtime.h>
#include <cuda_fp16.h>
#include <cstdint>

// ---------------- problem constants ----------------
#define BB   2
#define SEQ  2048
#define DIM  1024
#define NH   16
#define HD   64
#define BNR  (BB*SEQ)        // 4096
#define QKVC (3*HD)          // 192
#define NQKV (NH*QKVC)       // 3072

// softmax scale folded into q at gemm1 epilogue: 0.125 * log2(e)
#define QSCALE 0.1803368801111204f

// ---------------- device scratch ----------------
__device__ __half g_x    [BNR * DIM];
__device__ __half g_wqkvT[NQKV * DIM];
__device__ __half g_woT  [DIM * DIM];
__device__ __half g_qkv  [BNR * NQKV];
__device__ __half g_sa   [BNR * DIM];
__device__ float  g_o0   [BNR * DIM];    // split-KV partial O (split 0)
__device__ float  g_o1   [BNR * DIM];    // split 1
__device__ float  g_l0   [BNR * NH];     // split-KV partial l
__device__ float  g_l1   [BNR * NH];

// split-KV schedule: 24 blocks per (b,h), sorted by cost desc.
__constant__ short c_qt[24] = {7,15,15,14,14,6,13,13,12,12,5,11,11,10,10,4,9,9,8,8,3,2,1,0};
__constant__ short c_k0[24] = {0,0,16,0,15,0,0,14,0,13,0,0,12,0,11,0,0,10,0,9,0,0,0,0};
__constant__ short c_k1[24] = {16,16,32,15,30,14,14,28,13,26,12,12,24,11,22,10,10,20,9,18,8,6,4,2};
__constant__ short c_md[24] = {0,1,2,1,2,0,1,2,1,2,0,1,2,1,2,0,1,2,1,2,0,0,0,0};

// ---------------- helpers ----------------
__device__ __forceinline__ uint32_t pack_h2(float hi, float lo) {
    uint32_t d; asm("cvt.rn.f16x2.f32 %0, %1, %2;" : "=r"(d) : "f"(hi), "f"(lo)); return d;
}
__device__ __forceinline__ uint32_t ex2_h2(uint32_t x) {
    uint32_t r; asm("ex2.approx.f16x2 %0, %1;" : "=r"(r) : "r"(x)); return r;
}
__device__ __forceinline__ uint32_t hadd2u(uint32_t a, uint32_t b) {
    uint32_t r; asm("add.f16x2 %0, %1, %2;" : "=r"(r) : "r"(a), "r"(b)); return r;
}
__device__ __forceinline__ uint32_t smem_u32(const void* p) {
    uint32_t a;
    asm("{ .reg .u64 t; cvta.to.shared.u64 t, %1; cvt.u32.u64 %0, t; }" : "=r"(a) : "l"(p));
    return a;
}
#define CP16(dst, src) asm volatile("cp.async.cg.shared.global [%0], [%1], 16;" :: "r"(dst), "l"(src) : "memory")
#define CP_COMMIT()    asm volatile("cp.async.commit_group;" ::: "memory")
#define CP_WAIT1()     asm volatile("cp.async.wait_group 1;" ::: "memory")

__device__ __forceinline__ void mma_f16(float& d0, float& d1, float& d2, float& d3,
                                        uint32_t a0, uint32_t a1, uint32_t a2, uint32_t a3,
                                        uint32_t b0, uint32_t b1)
{
    asm volatile("mma.sync.aligned.m16n8k16.row.col.f32.f16.f16.f32 "
                 "{%0,%1,%2,%3}, {%4,%5,%6,%7}, {%8,%9}, {%0,%1,%2,%3};"
                 : "+f"(d0), "+f"(d1), "+f"(d2), "+f"(d3)
                 : "r"(a0), "r"(a1), "r"(a2), "r"(a3), "r"(b0), "r"(b1));
}
__device__ __forceinline__ void ldsm4(uint32_t& r0, uint32_t& r1, uint32_t& r2, uint32_t& r3,
                                      uint32_t addr)
{
    asm volatile("ldmatrix.sync.aligned.m8n8.x4.shared.b16 {%0,%1,%2,%3}, [%4];"
                 : "=r"(r0), "=r"(r1), "=r"(r2), "=r"(r3) : "r"(addr));
}
__device__ __forceinline__ void ldsm4t(uint32_t& r0, uint32_t& r1, uint32_t& r2, uint32_t& r3,
                                       uint32_t addr)
{
    asm volatile("ldmatrix.sync.aligned.m8n8.x4.trans.shared.b16 {%0,%1,%2,%3}, [%4];"
                 : "=r"(r0), "=r"(r1), "=r"(r2), "=r"(r3) : "r"(addr));
}

// ---------------- fused prep: x->half (2 f4/thr), coalesced transposes -------------
// grid 4096: [0,2048) x cvt; [2048,3584) wqkv transpose 64x32; [3584,4096) wo.
__global__ void prep_kernel(const float* __restrict__ x,
                            const float* __restrict__ Wqkv,
                            const float* __restrict__ Wo)
{
    __shared__ float t[32][65];   // t[c][r] tile: c=0..31 input cols, r=0..63 input rows
    const int b = blockIdx.x, tid = threadIdx.x;

    if (b < 2048) {
        int i = b * 512 + tid;
        float4 v0 = ((const float4*)x)[i];
        float4 v1 = ((const float4*)x)[i + 256];
        uint2 o0 = { pack_h2(v0.y, v0.x), pack_h2(v0.w, v0.z) };
        uint2 o1 = { pack_h2(v1.y, v1.x), pack_h2(v1.w, v1.z) };
        ((uint2*)g_x)[i] = o0;
        ((uint2*)g_x)[i + 256] = o1;
        return;
    }

    const float* inz; __half* outz; int C, bx, by;
    const int R = DIM;
    if (b < 3584) {
        int bb = b - 2048;               // 1536 = 16 z * 96
        int z = bb / 96, rem = bb % 96;
        int bxi = rem % 6, byi = rem / 6; // 6 col-tiles(32) x 16 row-tiles(64)
        C = QKVC; bx = bxi * 32; by = byi * 64;
        inz = Wqkv + (size_t)z * R * C;
        outz = g_wqkvT + (size_t)z * R * C;
    } else {
        int bb = b - 3584;               // 512 = 32 col-tiles x 16 row-tiles
        int bxi = bb & 31, byi = bb >> 5;
        C = DIM; bx = bxi * 32; by = byi * 64;
        inz = Wo; outz = g_woT;
    }
    const int tx = tid & 31, ty = tid >> 5;
    // load 64 rows x 32 cols; t[c][r]
#pragma unroll
    for (int j = 0; j < 8; j++) {
        int lr = ty + j * 8;
        t[tx][lr] = inz[(size_t)(by + lr) * C + bx + tx];
    }
    __syncthreads();
    // write out[c][r]: each warp-row writes 64 consecutive halves (128B) per i
#pragma unroll
    for (int i = ty; i < 32; i += 8) {
        uint32_t v = pack_h2(t[i][2 * tx + 1], t[i][2 * tx]);
        *(uint32_t*)&outz[(size_t)(bx + i) * R + by + 2 * tx] = v;
    }
}

// ================= fp16 mma GEMM: BK=64, 3-stage cp.async, 128B-row swizzle ==========
#define GEMM_SMEM (3 * 32768)

template<int MODE>   // 0: float out; 1: half out with q-scale (qkv)
__global__ __launch_bounds__(256, 2)
void gemm_h(const __half* __restrict__ A, const __half* __restrict__ Bt,
            const float* __restrict__ bias, void* __restrict__ Cv, int K, int N)
{
    extern __shared__ char smc[];
    const int tid = threadIdx.x, lane = tid & 31, wid = tid >> 5;
    const int warpM = (wid & 3) * 32, warpN = (wid >> 2) * 64;
    const int m0 = blockIdx.y * 128, n0 = blockIdx.x * 128;
    const int gr = lane >> 2, gc = lane & 3;
    const uint32_t sbase = smem_u32(smc);

    const int crow = tid >> 3, cg = tid & 7;
    const uint32_t cdst = (uint32_t)(crow * 128 + ((cg ^ (crow & 7)) << 4));
    const __half* Asrc = A + (size_t)(m0 + crow) * K + cg * 8;
    const __half* Bsrc = Bt + (size_t)(n0 + crow) * K + cg * 8;

    const int a_r = warpM + (lane & 15);
    const uint32_t aX = (uint32_t)(a_r & 7), agsel = (uint32_t)(lane >> 4);
    const int b_r = warpN + ((lane >> 4) << 3) + (lane & 7);
    const uint32_t bX = (uint32_t)(lane & 7), bgsel = (uint32_t)((lane >> 3) & 1);

    float acc[2][8][4];
#pragma unroll
    for (int mi = 0; mi < 2; mi++)
#pragma unroll
        for (int ni = 0; ni < 8; ni++)
#pragma unroll
            for (int q = 0; q < 4; q++) acc[mi][ni][q] = 0.f;

    const int NC = K / 64;

    auto issue = [&](int c, int st) {
        const uint32_t stb = sbase + (uint32_t)(st * 32768);
        const __half* Ap = Asrc + c * 64;
        const __half* Bp = Bsrc + c * 64;
#pragma unroll
        for (int t = 0; t < 4; t++) {
            CP16(stb + cdst + (uint32_t)(t * 4096), Ap + (size_t)t * 32 * K);
            CP16(stb + 16384u + cdst + (uint32_t)(t * 4096), Bp + (size_t)t * 32 * K);
        }
    };

    issue(0, 0); CP_COMMIT();
    issue(1, 1); CP_COMMIT();

    for (int c = 0; c < NC; c++) {
        const int st = c % 3;
        CP_WAIT1();
        __syncthreads();
        if (c + 2 < NC) issue(c + 2, (c + 2) % 3);
        CP_COMMIT();

        const uint32_t stb = sbase + (uint32_t)(st * 32768);
        const uint32_t aBase = stb + (uint32_t)(a_r * 128);
        const uint32_t bBase = stb + 16384u + (uint32_t)(b_r * 128);
#pragma unroll
        for (int ks = 0; ks < 4; ks++) {
            const uint32_t ac = ((2u * ks + agsel) ^ aX) << 4;
            const uint32_t bc = ((2u * ks + bgsel) ^ bX) << 4;
            uint32_t a[2][4], b[8][2];
            ldsm4(a[0][0], a[0][1], a[0][2], a[0][3], aBase + ac);
            ldsm4(a[1][0], a[1][1], a[1][2], a[1][3], aBase + 2048u + ac);
#pragma unroll
            for (int p = 0; p < 4; p++)
                ldsm4(b[2*p][0], b[2*p][1], b[2*p+1][0], b[2*p+1][1],
                      bBase + (uint32_t)(p * 2048) + bc);
#pragma unroll
            for (int mi = 0; mi < 2; mi++)
#pragma unroll
                for (int ni = 0; ni < 8; ni++)
                    mma_f16(acc[mi][ni][0], acc[mi][ni][1], acc[mi][ni][2], acc[mi][ni][3],
                            a[mi][0], a[mi][1], a[mi][2], a[mi][3], b[ni][0], b[ni][1]);
        }
    }

#pragma unroll
    for (int mi = 0; mi < 2; mi++) {
        int row = m0 + warpM + mi * 16 + gr;
#pragma unroll
        for (int ni = 0; ni < 8; ni++) {
            int col = n0 + warpN + ni * 8 + gc * 2;
            float2 bsv = *(const float2*)(bias + col);
            float v00 = acc[mi][ni][0] + bsv.x, v01 = acc[mi][ni][1] + bsv.y;
            float v10 = acc[mi][ni][2] + bsv.x, v11 = acc[mi][ni][3] + bsv.y;
            if (MODE == 1) {
                int j = col % QKVC;
                float sc = (j >= 64 && j < 128) ? QSCALE : 1.0f;
                v00 *= sc; v01 *= sc; v10 *= sc; v11 *= sc;
                __half* Ch = (__half*)Cv;
                *(uint32_t*)&Ch[(size_t)row * N + col]       = pack_h2(v01, v00);
                *(uint32_t*)&Ch[(size_t)(row + 8) * N + col] = pack_h2(v11, v10);
            } else {
                float* Cf = (float*)Cv;
                float2 w0 = { v00, v01 }, w1 = { v10, v11 };
                *(float2*)&Cf[(size_t)row * N + col] = w0;
                *(float2*)&Cf[(size_t)(row + 8) * N + col] = w1;
            }
        }
    }
}

// ================= fp16 flash attention: split-KV, h2 exp, 3 CTA/SM =================
#define ATTN_SMEM 65536

__global__ __launch_bounds__(128, 3)
void attn_h()
{
    extern __shared__ char smc[];
    const int tid = threadIdx.x, lane = tid & 31, wid = tid >> 5;
    const int idx = blockIdx.x;
    const int qt = c_qt[idx], kt0 = c_k0[idx], kt1 = c_k1[idx], md = c_md[idx];
    const int h = blockIdx.y, b = blockIdx.z;
    const int bn0 = b * SEQ;
    const int colK = h * QKVC, colQ = colK + HD, colV = colK + 2 * HD;
    const int q0 = qt * 128;
    const int gr = lane >> 2, gc = lane & 3;
    const int qrow = wid * 32 + gr;

    const uint32_t sbase = smem_u32(smc);
    const uint32_t uQ = sbase;
    const uint32_t uKV = sbase + 16384u;

    const int crow = tid >> 3, cg = tid & 7;
    const uint32_t cdst = (uint32_t)(crow * 128 + ((cg ^ (crow & 7)) << 4));

    auto issue_kv = [&](int kt, int st) {
        const __half* Kp = g_qkv + (size_t)(bn0 + kt * 64 + crow) * NQKV + colK + cg * 8;
        const __half* Vp = g_qkv + (size_t)(bn0 + kt * 64 + crow) * NQKV + colV + cg * 8;
        const uint32_t stb = uKV + (uint32_t)(st * 16384);
#pragma unroll
        for (int t = 0; t < 4; t++) {
            CP16(stb + cdst + (uint32_t)(t * 2048), Kp + (size_t)t * 16 * NQKV);
            CP16(stb + 8192u + cdst + (uint32_t)(t * 2048), Vp + (size_t)t * 16 * NQKV);
        }
    };

    {
        const __half* Qp = g_qkv + (size_t)(bn0 + q0 + crow) * NQKV + colQ + cg * 8;
#pragma unroll
        for (int t = 0; t < 8; t++)
            CP16(uQ + cdst + (uint32_t)(t * 2048), Qp + (size_t)t * 16 * NQKV);
    }
    issue_kv(kt0, 0); CP_COMMIT();
    issue_kv(kt0 + 1, 1); CP_COMMIT();

    const int qa_r = wid * 32 + (lane & 15);
    const uint32_t qX = (uint32_t)(qa_r & 7), agsel = (uint32_t)(lane >> 4);
    const uint32_t qBase = uQ + (uint32_t)(qa_r * 128);
    const int kb_r = ((lane >> 4) << 3) + (lane & 7);
    const uint32_t kX = (uint32_t)(lane & 7), bgsel = (uint32_t)((lane >> 3) & 1);
    const int v_r = (((lane >> 3) & 1) << 3) + (lane & 7);
    const uint32_t vX = (uint32_t)(lane & 7), vgsel = (uint32_t)(lane >> 4);

    float accO[2][8][4];
#pragma unroll
    for (int mi = 0; mi < 2; mi++)
#pragma unroll
        for (int ni = 0; ni < 8; ni++)
#pragma unroll
            for (int q = 0; q < 4; q++) accO[mi][ni][q] = 0.f;
    float ls[2][2] = { {0.f, 0.f}, {0.f, 0.f} };

    const int lastq = q0 + wid * 32 + 31;

    for (int kt = kt0; kt < kt1; kt++) {
        const int st = (kt - kt0) % 3;
        CP_WAIT1();
        __syncthreads();
        if (kt + 2 < kt1) issue_kv(kt + 2, (kt - kt0 + 2) % 3);
        CP_COMMIT();

        if (kt * 64 > lastq) continue;

        const uint32_t stK = uKV + (uint32_t)(st * 16384);
        const uint32_t stV = stK + 8192u;

        // ---- S = Q @ K^T ----
        float s[2][8][4];
#pragma unroll
        for (int mi = 0; mi < 2; mi++)
#pragma unroll
            for (int ni = 0; ni < 8; ni++)
#pragma unroll
                for (int q = 0; q < 4; q++) s[mi][ni][q] = 0.f;
#pragma unroll
        for (int ks = 0; ks < 4; ks++) {
            const uint32_t ac = ((2u * ks + agsel) ^ qX) << 4;
            const uint32_t bc = ((2u * ks + bgsel) ^ kX) << 4;
            uint32_t a[2][4], bk[8][2];
            ldsm4(a[0][0], a[0][1], a[0][2], a[0][3], qBase + ac);
            ldsm4(a[1][0], a[1][1], a[1][2], a[1][3], qBase + 2048u + ac);
#pragma unroll
            for (int p = 0; p < 4; p++)
                ldsm4(bk[2*p][0], bk[2*p][1], bk[2*p+1][0], bk[2*p+1][1],
                      stK + (uint32_t)((kb_r + p * 16) * 128) + bc);
#pragma unroll
            for (int ni = 0; ni < 8; ni++) {
                mma_f16(s[0][ni][0], s[0][ni][1], s[0][ni][2], s[0][ni][3],
                        a[0][0], a[0][1], a[0][2], a[0][3], bk[ni][0], bk[ni][1]);
                mma_f16(s[1][ni][0], s[1][ni][1], s[1][ni][2], s[1][ni][3],
                        a[1][0], a[1][1], a[1][2], a[1][3], bk[ni][0], bk[ni][1]);
            }
        }

        // ---- causal mask ----
        if (kt >= 2 * qt) {
            const int kb = kt * 64;
#pragma unroll
            for (int mi = 0; mi < 2; mi++) {
                const int qg = q0 + qrow + mi * 16;
#pragma unroll
                for (int ni = 0; ni < 8; ni++) {
                    int kc = kb + ni * 8 + gc * 2;
                    if (kc     > qg    ) s[mi][ni][0] = -1e30f;
                    if (kc + 1 > qg    ) s[mi][ni][1] = -1e30f;
                    if (kc     > qg + 8) s[mi][ni][2] = -1e30f;
                    if (kc + 1 > qg + 8) s[mi][ni][3] = -1e30f;
                }
            }
        }

        // ---- pack s to h2, then P = ex2.f16x2 ----
        uint32_t pa[2][4][4];
#pragma unroll
        for (int mi = 0; mi < 2; mi++)
#pragma unroll
            for (int ks = 0; ks < 4; ks++) {
                pa[mi][ks][0] = ex2_h2(pack_h2(s[mi][2*ks][1],   s[mi][2*ks][0]));
                pa[mi][ks][1] = ex2_h2(pack_h2(s[mi][2*ks][3],   s[mi][2*ks][2]));
                pa[mi][ks][2] = ex2_h2(pack_h2(s[mi][2*ks+1][1], s[mi][2*ks+1][0]));
                pa[mi][ks][3] = ex2_h2(pack_h2(s[mi][2*ks+1][3], s[mi][2*ks+1][2]));
            }

        // ---- tile-local row sums in h2, folded into fp32 ----
#pragma unroll
        for (int mi = 0; mi < 2; mi++) {
            uint32_t h0 = hadd2u(hadd2u(pa[mi][0][0], pa[mi][0][2]),
                                 hadd2u(pa[mi][1][0], pa[mi][1][2]));
            uint32_t h0b = hadd2u(hadd2u(pa[mi][2][0], pa[mi][2][2]),
                                  hadd2u(pa[mi][3][0], pa[mi][3][2]));
            uint32_t h1 = hadd2u(hadd2u(pa[mi][0][1], pa[mi][0][3]),
                                 hadd2u(pa[mi][1][1], pa[mi][1][3]));
            uint32_t h1b = hadd2u(hadd2u(pa[mi][2][1], pa[mi][2][3]),
                                  hadd2u(pa[mi][3][1], pa[mi][3][3]));
            float2 f0 = __half22float2(*(const __half2*)&h0);
            float2 f0b = __half22float2(*(const __half2*)&h0b);
            float2 f1 = __half22float2(*(const __half2*)&h1);
            float2 f1b = __half22float2(*(const __half2*)&h1b);
            ls[mi][0] += (f0.x + f0.y) + (f0b.x + f0b.y);
            ls[mi][1] += (f1.x + f1.y) + (f1b.x + f1b.y);
        }

        // ---- O += P @ V ----
#pragma unroll
        for (int ks = 0; ks < 4; ks++) {
            uint32_t bv[8][2];
#pragma unroll
            for (int p = 0; p < 4; p++) {
                const uint32_t vc = ((2u * p + vgsel) ^ vX) << 4;
                ldsm4t(bv[2*p][0], bv[2*p][1], bv[2*p+1][0], bv[2*p+1][1],
                       stV + (uint32_t)((v_r + ks * 16) * 128) + vc);
            }
#pragma unroll
            for (int ni = 0; ni < 8; ni++) {
                mma_f16(accO[0][ni][0], accO[0][ni][1], accO[0][ni][2], accO[0][ni][3],
                        pa[0][ks][0], pa[0][ks][1], pa[0][ks][2], pa[0][ks][3],
                        bv[ni][0], bv[ni][1]);
                mma_f16(accO[1][ni][0], accO[1][ni][1], accO[1][ni][2], accO[1][ni][3],
                        pa[1][ks][0], pa[1][ks][1], pa[1][ks][2], pa[1][ks][3],
                        bv[ni][0], bv[ni][1]);
            }
        }
    }

    // ---- epilogue ----
#pragma unroll
    for (int mi = 0; mi < 2; mi++) {
        ls[mi][0] += __shfl_xor_sync(0xffffffffu, ls[mi][0], 1);
        ls[mi][0] += __shfl_xor_sync(0xffffffffu, ls[mi][0], 2);
        ls[mi][1] += __shfl_xor_sync(0xffffffffu, ls[mi][1], 1);
        ls[mi][1] += __shfl_xor_sync(0xffffffffu, ls[mi][1], 2);
    }
    if (md == 0) {
#pragma unroll
        for (int mi = 0; mi < 2; mi++) {
            float inv0 = 1.f / ls[mi][0], inv1 = 1.f / ls[mi][1];
            int row = bn0 + q0 + qrow + mi * 16;
#pragma unroll
            for (int ni = 0; ni < 8; ni++) {
                int col = h * HD + ni * 8 + gc * 2;
                *(uint32_t*)&g_sa[(size_t)row * DIM + col] =
                    pack_h2(accO[mi][ni][1] * inv0, accO[mi][ni][0] * inv0);
                *(uint32_t*)&g_sa[(size_t)(row + 8) * DIM + col] =
                    pack_h2(accO[mi][ni][3] * inv1, accO[mi][ni][2] * inv1);
            }
        }
    } else {
        float* Po = (md == 1) ? g_o0 : g_o1;
        float* Pl = (md == 1) ? g_l0 : g_l1;
#pragma unroll
        for (int mi = 0; mi < 2; mi++) {
            int row = bn0 + q0 + qrow + mi * 16;
            if (gc == 0) {
                Pl[(size_t)row * NH + h]       = ls[mi][0];
                Pl[(size_t)(row + 8) * NH + h] = ls[mi][1];
            }
#pragma unroll
            for (int ni = 0; ni < 8; ni++) {
                int col = h * HD + ni * 8 + gc * 2;
                float2 w0 = { accO[mi][ni][0], accO[mi][ni][1] };
                float2 w1 = { accO[mi][ni][2], accO[mi][ni][3] };
                *(float2*)&Po[(size_t)row * DIM + col] = w0;
                *(float2*)&Po[(size_t)(row + 8) * DIM + col] = w1;
            }
        }
    }
}

// ---------------- split-KV combine: 4 rows/block, 16 floats/thread -----------------
__global__ void combine_kernel()
{
    const int b = blockIdx.x >> 8;
    const int rl = 1024 + ((blockIdx.x & 255) << 2) + (threadIdx.x >> 6);
    const size_t row = (size_t)b * SEQ + rl;
    const int col = (threadIdx.x & 63) * 16;
    const int h = col >> 6;
    const float inv = 1.f / (g_l0[row * NH + h] + g_l1[row * NH + h]);
    const float* p0 = &g_o0[row * DIM + col];
    const float* p1 = &g_o1[row * DIM + col];
    __half* po = &g_sa[row * DIM + col];
#pragma unroll
    for (int t = 0; t < 4; t++) {
        float4 a = *(const float4*)(p0 + t * 4);
        float4 c = *(const float4*)(p1 + t * 4);
        uint2 o = { pack_h2((a.y + c.y) * inv, (a.x + c.x) * inv),
                    pack_h2((a.w + c.w) * inv, (a.z + c.z) * inv) };
        *(uint2*)(po + t * 4) = o;
    }
}

// ---------------- launch ----------------
extern "C" void kernel_launch(void* const* d_in, const int* in_sizes, int n_in,
                              void* d_out, int out_size)
{
    const float* x    = (const float*)d_in[0];
    const float* Wqkv = (const float*)d_in[1];
    const float* bqkv = (const float*)d_in[2];
    const float* Wo   = (const float*)d_in[3];
    const float* bo   = (const float*)d_in[4];
    float* out = (float*)d_out;

    __half *xh, *wqkvT, *woT, *qkv, *sa;
    cudaGetSymbolAddress((void**)&xh,    g_x);
    cudaGetSymbolAddress((void**)&wqkvT, g_wqkvT);
    cudaGetSymbolAddress((void**)&woT,   g_woT);
    cudaGetSymbolAddress((void**)&qkv,   g_qkv);
    cudaGetSymbolAddress((void**)&sa,    g_sa);

    cudaFuncSetAttribute(gemm_h<1>, cudaFuncAttributeMaxDynamicSharedMemorySize, GEMM_SMEM);
    cudaFuncSetAttribute(gemm_h<0>, cudaFuncAttributeMaxDynamicSharedMemorySize, GEMM_SMEM);
    cudaFuncSetAttribute(attn_h, cudaFuncAttributeMaxDynamicSharedMemorySize, ATTN_SMEM);

    prep_kernel<<<4096, 256>>>(x, Wqkv, Wo);
    gemm_h<1><<<dim3(NQKV / 128, BNR / 128), 256, GEMM_SMEM>>>(xh, wqkvT, bqkv, qkv, DIM, NQKV);
    attn_h<<<dim3(24, NH, BB), 128, ATTN_SMEM>>>();
    combine_kernel<<<512, 256>>>();
    gemm_h<0><<<dim3(DIM / 128, BNR / 128), 256, GEMM_SMEM>>>(sa, woT, bo, out, DIM, DIM);
}

// round 16
// speedup vs baseline: 1.0794x; 1.0112x over previous
#include <cuda_runtime.h>
#include <cuda_fp16.h>
#include <cstdint>

// ---------------- problem constants ----------------
#define BB   2
#define SEQ  2048
#define DIM  1024
#define NH   16
#define HD   64
#define BNR  (BB*SEQ)        // 4096
#define QKVC (3*HD)          // 192
#define NQKV (NH*QKVC)       // 3072

// softmax scale folded into q at gemm1 epilogue: 0.125 * log2(e)
#define QSCALE 0.1803368801111204f

// ---------------- device scratch ----------------
__device__ __half g_x    [BNR * DIM];
__device__ __half g_wqkvT[NQKV * DIM];
__device__ __half g_woT  [DIM * DIM];
__device__ __half g_qkv  [BNR * NQKV];
__device__ __half g_sa   [BNR * DIM];
__device__ __half g_o0   [BNR * DIM];    // split-KV partial O (split 0, fp16)
__device__ __half g_o1   [BNR * DIM];    // split 1
__device__ float  g_l0   [BNR * NH];     // split-KV partial l (fp32)
__device__ float  g_l1   [BNR * NH];

// split-KV schedule: 24 blocks per (b,h), sorted by cost desc.
__constant__ short c_qt[24] = {7,15,15,14,14,6,13,13,12,12,5,11,11,10,10,4,9,9,8,8,3,2,1,0};
__constant__ short c_k0[24] = {0,0,16,0,15,0,0,14,0,13,0,0,12,0,11,0,0,10,0,9,0,0,0,0};
__constant__ short c_k1[24] = {16,16,32,15,30,14,14,28,13,26,12,12,24,11,22,10,10,20,9,18,8,6,4,2};
__constant__ short c_md[24] = {0,1,2,1,2,0,1,2,1,2,0,1,2,1,2,0,1,2,1,2,0,0,0,0};

// ---------------- helpers ----------------
__device__ __forceinline__ uint32_t pack_h2(float hi, float lo) {
    uint32_t d; asm("cvt.rn.f16x2.f32 %0, %1, %2;" : "=r"(d) : "f"(hi), "f"(lo)); return d;
}
__device__ __forceinline__ uint32_t ex2_h2(uint32_t x) {
    uint32_t r; asm("ex2.approx.f16x2 %0, %1;" : "=r"(r) : "r"(x)); return r;
}
__device__ __forceinline__ uint32_t hadd2u(uint32_t a, uint32_t b) {
    uint32_t r; asm("add.f16x2 %0, %1, %2;" : "=r"(r) : "r"(a), "r"(b)); return r;
}
__device__ __forceinline__ uint32_t smem_u32(const void* p) {
    uint32_t a;
    asm("{ .reg .u64 t; cvta.to.shared.u64 t, %1; cvt.u32.u64 %0, t; }" : "=r"(a) : "l"(p));
    return a;
}
#define CP16(dst, src) asm volatile("cp.async.cg.shared.global [%0], [%1], 16;" :: "r"(dst), "l"(src) : "memory")
#define CP_COMMIT()    asm volatile("cp.async.commit_group;" ::: "memory")
#define CP_WAIT1()     asm volatile("cp.async.wait_group 1;" ::: "memory")

__device__ __forceinline__ void mma_f16(float& d0, float& d1, float& d2, float& d3,
                                        uint32_t a0, uint32_t a1, uint32_t a2, uint32_t a3,
                                        uint32_t b0, uint32_t b1)
{
    asm volatile("mma.sync.aligned.m16n8k16.row.col.f32.f16.f16.f32 "
                 "{%0,%1,%2,%3}, {%4,%5,%6,%7}, {%8,%9}, {%0,%1,%2,%3};"
                 : "+f"(d0), "+f"(d1), "+f"(d2), "+f"(d3)
                 : "r"(a0), "r"(a1), "r"(a2), "r"(a3), "r"(b0), "r"(b1));
}
__device__ __forceinline__ void ldsm4(uint32_t& r0, uint32_t& r1, uint32_t& r2, uint32_t& r3,
                                      uint32_t addr)
{
    asm volatile("ldmatrix.sync.aligned.m8n8.x4.shared.b16 {%0,%1,%2,%3}, [%4];"
                 : "=r"(r0), "=r"(r1), "=r"(r2), "=r"(r3) : "r"(addr));
}
__device__ __forceinline__ void ldsm4t(uint32_t& r0, uint32_t& r1, uint32_t& r2, uint32_t& r3,
                                       uint32_t addr)
{
    asm volatile("ldmatrix.sync.aligned.m8n8.x4.trans.shared.b16 {%0,%1,%2,%3}, [%4];"
                 : "=r"(r0), "=r"(r1), "=r"(r2), "=r"(r3) : "r"(addr));
}

// ---------------- fused prep: x->half (2 f4/thr), coalesced transposes -------------
__global__ void prep_kernel(const float* __restrict__ x,
                            const float* __restrict__ Wqkv,
                            const float* __restrict__ Wo)
{
    __shared__ float t[32][65];
    const int b = blockIdx.x, tid = threadIdx.x;

    if (b < 2048) {
        int i = b * 512 + tid;
        float4 v0 = ((const float4*)x)[i];
        float4 v1 = ((const float4*)x)[i + 256];
        uint2 o0 = { pack_h2(v0.y, v0.x), pack_h2(v0.w, v0.z) };
        uint2 o1 = { pack_h2(v1.y, v1.x), pack_h2(v1.w, v1.z) };
        ((uint2*)g_x)[i] = o0;
        ((uint2*)g_x)[i + 256] = o1;
        return;
    }

    const float* inz; __half* outz; int C, bx, by;
    const int R = DIM;
    if (b < 3584) {
        int bb = b - 2048;
        int z = bb / 96, rem = bb % 96;
        int bxi = rem % 6, byi = rem / 6;
        C = QKVC; bx = bxi * 32; by = byi * 64;
        inz = Wqkv + (size_t)z * R * C;
        outz = g_wqkvT + (size_t)z * R * C;
    } else {
        int bb = b - 3584;
        int bxi = bb & 31, byi = bb >> 5;
        C = DIM; bx = bxi * 32; by = byi * 64;
        inz = Wo; outz = g_woT;
    }
    const int tx = tid & 31, ty = tid >> 5;
#pragma unroll
    for (int j = 0; j < 8; j++) {
        int lr = ty + j * 8;
        t[tx][lr] = inz[(size_t)(by + lr) * C + bx + tx];
    }
    __syncthreads();
#pragma unroll
    for (int i = ty; i < 32; i += 8) {
        uint32_t v = pack_h2(t[i][2 * tx + 1], t[i][2 * tx]);
        *(uint32_t*)&outz[(size_t)(bx + i) * R + by + 2 * tx] = v;
    }
}

// ================= fp16 mma GEMM: BK=64, 3-stage cp.async, 128B-row swizzle ==========
#define GEMM_SMEM (3 * 32768)

template<int MODE>   // 0: float out; 1: half out with q-scale (qkv)
__global__ __launch_bounds__(256, 2)
void gemm_h(const __half* __restrict__ A, const __half* __restrict__ Bt,
            const float* __restrict__ bias, void* __restrict__ Cv, int K, int N)
{
    extern __shared__ char smc[];
    const int tid = threadIdx.x, lane = tid & 31, wid = tid >> 5;
    const int warpM = (wid & 3) * 32, warpN = (wid >> 2) * 64;
    const int m0 = blockIdx.y * 128, n0 = blockIdx.x * 128;
    const int gr = lane >> 2, gc = lane & 3;
    const uint32_t sbase = smem_u32(smc);

    const int crow = tid >> 3, cg = tid & 7;
    const uint32_t cdst = (uint32_t)(crow * 128 + ((cg ^ (crow & 7)) << 4));
    const __half* Asrc = A + (size_t)(m0 + crow) * K + cg * 8;
    const __half* Bsrc = Bt + (size_t)(n0 + crow) * K + cg * 8;

    const int a_r = warpM + (lane & 15);
    const uint32_t aX = (uint32_t)(a_r & 7), agsel = (uint32_t)(lane >> 4);
    const int b_r = warpN + ((lane >> 4) << 3) + (lane & 7);
    const uint32_t bX = (uint32_t)(lane & 7), bgsel = (uint32_t)((lane >> 3) & 1);

    float acc[2][8][4];
#pragma unroll
    for (int mi = 0; mi < 2; mi++)
#pragma unroll
        for (int ni = 0; ni < 8; ni++)
#pragma unroll
            for (int q = 0; q < 4; q++) acc[mi][ni][q] = 0.f;

    const int NC = K / 64;

    auto issue = [&](int c, int st) {
        const uint32_t stb = sbase + (uint32_t)(st * 32768);
        const __half* Ap = Asrc + c * 64;
        const __half* Bp = Bsrc + c * 64;
#pragma unroll
        for (int t = 0; t < 4; t++) {
            CP16(stb + cdst + (uint32_t)(t * 4096), Ap + (size_t)t * 32 * K);
            CP16(stb + 16384u + cdst + (uint32_t)(t * 4096), Bp + (size_t)t * 32 * K);
        }
    };

    issue(0, 0); CP_COMMIT();
    issue(1, 1); CP_COMMIT();

    for (int c = 0; c < NC; c++) {
        const int st = c % 3;
        CP_WAIT1();
        __syncthreads();
        if (c + 2 < NC) issue(c + 2, (c + 2) % 3);
        CP_COMMIT();

        const uint32_t stb = sbase + (uint32_t)(st * 32768);
        const uint32_t aBase = stb + (uint32_t)(a_r * 128);
        const uint32_t bBase = stb + 16384u + (uint32_t)(b_r * 128);
#pragma unroll
        for (int ks = 0; ks < 4; ks++) {
            const uint32_t ac = ((2u * ks + agsel) ^ aX) << 4;
            const uint32_t bc = ((2u * ks + bgsel) ^ bX) << 4;
            uint32_t a[2][4], b[8][2];
            ldsm4(a[0][0], a[0][1], a[0][2], a[0][3], aBase + ac);
            ldsm4(a[1][0], a[1][1], a[1][2], a[1][3], aBase + 2048u + ac);
#pragma unroll
            for (int p = 0; p < 4; p++)
                ldsm4(b[2*p][0], b[2*p][1], b[2*p+1][0], b[2*p+1][1],
                      bBase + (uint32_t)(p * 2048) + bc);
#pragma unroll
            for (int mi = 0; mi < 2; mi++)
#pragma unroll
                for (int ni = 0; ni < 8; ni++)
                    mma_f16(acc[mi][ni][0], acc[mi][ni][1], acc[mi][ni][2], acc[mi][ni][3],
                            a[mi][0], a[mi][1], a[mi][2], a[mi][3], b[ni][0], b[ni][1]);
        }
    }

#pragma unroll
    for (int mi = 0; mi < 2; mi++) {
        int row = m0 + warpM + mi * 16 + gr;
#pragma unroll
        for (int ni = 0; ni < 8; ni++) {
            int col = n0 + warpN + ni * 8 + gc * 2;
            float2 bsv = *(const float2*)(bias + col);
            float v00 = acc[mi][ni][0] + bsv.x, v01 = acc[mi][ni][1] + bsv.y;
            float v10 = acc[mi][ni][2] + bsv.x, v11 = acc[mi][ni][3] + bsv.y;
            if (MODE == 1) {
                int j = col % QKVC;
                float sc = (j >= 64 && j < 128) ? QSCALE : 1.0f;
                v00 *= sc; v01 *= sc; v10 *= sc; v11 *= sc;
                __half* Ch = (__half*)Cv;
                *(uint32_t*)&Ch[(size_t)row * N + col]       = pack_h2(v01, v00);
                *(uint32_t*)&Ch[(size_t)(row + 8) * N + col] = pack_h2(v11, v10);
            } else {
                float* Cf = (float*)Cv;
                float2 w0 = { v00, v01 }, w1 = { v10, v11 };
                *(float2*)&Cf[(size_t)row * N + col] = w0;
                *(float2*)&Cf[(size_t)(row + 8) * N + col] = w1;
            }
        }
    }
}

// ================= fp16 flash attention: split-KV (fp16 partials), h2 exp ==========
#define ATTN_SMEM 65536

__global__ __launch_bounds__(128, 3)
void attn_h()
{
    extern __shared__ char smc[];
    const int tid = threadIdx.x, lane = tid & 31, wid = tid >> 5;
    const int idx = blockIdx.x;
    const int qt = c_qt[idx], kt0 = c_k0[idx], kt1 = c_k1[idx], md = c_md[idx];
    const int h = blockIdx.y, b = blockIdx.z;
    const int bn0 = b * SEQ;
    const int colK = h * QKVC, colQ = colK + HD, colV = colK + 2 * HD;
    const int q0 = qt * 128;
    const int gr = lane >> 2, gc = lane & 3;
    const int qrow = wid * 32 + gr;

    const uint32_t sbase = smem_u32(smc);
    const uint32_t uQ = sbase;
    const uint32_t uKV = sbase + 16384u;

    const int crow = tid >> 3, cg = tid & 7;
    const uint32_t cdst = (uint32_t)(crow * 128 + ((cg ^ (crow & 7)) << 4));

    auto issue_kv = [&](int kt, int st) {
        const __half* Kp = g_qkv + (size_t)(bn0 + kt * 64 + crow) * NQKV + colK + cg * 8;
        const __half* Vp = g_qkv + (size_t)(bn0 + kt * 64 + crow) * NQKV + colV + cg * 8;
        const uint32_t stb = uKV + (uint32_t)(st * 16384);
#pragma unroll
        for (int t = 0; t < 4; t++) {
            CP16(stb + cdst + (uint32_t)(t * 2048), Kp + (size_t)t * 16 * NQKV);
            CP16(stb + 8192u + cdst + (uint32_t)(t * 2048), Vp + (size_t)t * 16 * NQKV);
        }
    };

    {
        const __half* Qp = g_qkv + (size_t)(bn0 + q0 + crow) * NQKV + colQ + cg * 8;
#pragma unroll
        for (int t = 0; t < 8; t++)
            CP16(uQ + cdst + (uint32_t)(t * 2048), Qp + (size_t)t * 16 * NQKV);
    }
    issue_kv(kt0, 0); CP_COMMIT();
    issue_kv(kt0 + 1, 1); CP_COMMIT();

    const int qa_r = wid * 32 + (lane & 15);
    const uint32_t qX = (uint32_t)(qa_r & 7), agsel = (uint32_t)(lane >> 4);
    const uint32_t qBase = uQ + (uint32_t)(qa_r * 128);
    const int kb_r = ((lane >> 4) << 3) + (lane & 7);
    const uint32_t kX = (uint32_t)(lane & 7), bgsel = (uint32_t)((lane >> 3) & 1);
    const int v_r = (((lane >> 3) & 1) << 3) + (lane & 7);
    const uint32_t vX = (uint32_t)(lane & 7), vgsel = (uint32_t)(lane >> 4);

    float accO[2][8][4];
#pragma unroll
    for (int mi = 0; mi < 2; mi++)
#pragma unroll
        for (int ni = 0; ni < 8; ni++)
#pragma unroll
            for (int q = 0; q < 4; q++) accO[mi][ni][q] = 0.f;
    float ls[2][2] = { {0.f, 0.f}, {0.f, 0.f} };

    const int lastq = q0 + wid * 32 + 31;

    for (int kt = kt0; kt < kt1; kt++) {
        const int st = (kt - kt0) % 3;
        CP_WAIT1();
        __syncthreads();
        if (kt + 2 < kt1) issue_kv(kt + 2, (kt - kt0 + 2) % 3);
        CP_COMMIT();

        if (kt * 64 > lastq) continue;

        const uint32_t stK = uKV + (uint32_t)(st * 16384);
        const uint32_t stV = stK + 8192u;

        // ---- S = Q @ K^T ----
        float s[2][8][4];
#pragma unroll
        for (int mi = 0; mi < 2; mi++)
#pragma unroll
            for (int ni = 0; ni < 8; ni++)
#pragma unroll
                for (int q = 0; q < 4; q++) s[mi][ni][q] = 0.f;
#pragma unroll
        for (int ks = 0; ks < 4; ks++) {
            const uint32_t ac = ((2u * ks + agsel) ^ qX) << 4;
            const uint32_t bc = ((2u * ks + bgsel) ^ kX) << 4;
            uint32_t a[2][4], bk[8][2];
            ldsm4(a[0][0], a[0][1], a[0][2], a[0][3], qBase + ac);
            ldsm4(a[1][0], a[1][1], a[1][2], a[1][3], qBase + 2048u + ac);
#pragma unroll
            for (int p = 0; p < 4; p++)
                ldsm4(bk[2*p][0], bk[2*p][1], bk[2*p+1][0], bk[2*p+1][1],
                      stK + (uint32_t)((kb_r + p * 16) * 128) + bc);
#pragma unroll
            for (int ni = 0; ni < 8; ni++) {
                mma_f16(s[0][ni][0], s[0][ni][1], s[0][ni][2], s[0][ni][3],
                        a[0][0], a[0][1], a[0][2], a[0][3], bk[ni][0], bk[ni][1]);
                mma_f16(s[1][ni][0], s[1][ni][1], s[1][ni][2], s[1][ni][3],
                        a[1][0], a[1][1], a[1][2], a[1][3], bk[ni][0], bk[ni][1]);
            }
        }

        // ---- causal mask ----
        if (kt >= 2 * qt) {
            const int kb = kt * 64;
#pragma unroll
            for (int mi = 0; mi < 2; mi++) {
                const int qg = q0 + qrow + mi * 16;
#pragma unroll
                for (int ni = 0; ni < 8; ni++) {
                    int kc = kb + ni * 8 + gc * 2;
                    if (kc     > qg    ) s[mi][ni][0] = -1e30f;
                    if (kc + 1 > qg    ) s[mi][ni][1] = -1e30f;
                    if (kc     > qg + 8) s[mi][ni][2] = -1e30f;
                    if (kc + 1 > qg + 8) s[mi][ni][3] = -1e30f;
                }
            }
        }

        // ---- pack s to h2, then P = ex2.f16x2 ----
        uint32_t pa[2][4][4];
#pragma unroll
        for (int mi = 0; mi < 2; mi++)
#pragma unroll
            for (int ks = 0; ks < 4; ks++) {
                pa[mi][ks][0] = ex2_h2(pack_h2(s[mi][2*ks][1],   s[mi][2*ks][0]));
                pa[mi][ks][1] = ex2_h2(pack_h2(s[mi][2*ks][3],   s[mi][2*ks][2]));
                pa[mi][ks][2] = ex2_h2(pack_h2(s[mi][2*ks+1][1], s[mi][2*ks+1][0]));
                pa[mi][ks][3] = ex2_h2(pack_h2(s[mi][2*ks+1][3], s[mi][2*ks+1][2]));
            }

        // ---- tile-local row sums in h2, folded into fp32 ----
#pragma unroll
        for (int mi = 0; mi < 2; mi++) {
            uint32_t h0 = hadd2u(hadd2u(pa[mi][0][0], pa[mi][0][2]),
                                 hadd2u(pa[mi][1][0], pa[mi][1][2]));
            uint32_t h0b = hadd2u(hadd2u(pa[mi][2][0], pa[mi][2][2]),
                                  hadd2u(pa[mi][3][0], pa[mi][3][2]));
            uint32_t h1 = hadd2u(hadd2u(pa[mi][0][1], pa[mi][0][3]),
                                 hadd2u(pa[mi][1][1], pa[mi][1][3]));
            uint32_t h1b = hadd2u(hadd2u(pa[mi][2][1], pa[mi][2][3]),
                                  hadd2u(pa[mi][3][1], pa[mi][3][3]));
            float2 f0 = __half22float2(*(const __half2*)&h0);
            float2 f0b = __half22float2(*(const __half2*)&h0b);
            float2 f1 = __half22float2(*(const __half2*)&h1);
            float2 f1b = __half22float2(*(const __half2*)&h1b);
            ls[mi][0] += (f0.x + f0.y) + (f0b.x + f0b.y);
            ls[mi][1] += (f1.x + f1.y) + (f1b.x + f1b.y);
        }

        // ---- O += P @ V ----
#pragma unroll
        for (int ks = 0; ks < 4; ks++) {
            uint32_t bv[8][2];
#pragma unroll
            for (int p = 0; p < 4; p++) {
                const uint32_t vc = ((2u * p + vgsel) ^ vX) << 4;
                ldsm4t(bv[2*p][0], bv[2*p][1], bv[2*p+1][0], bv[2*p+1][1],
                       stV + (uint32_t)((v_r + ks * 16) * 128) + vc);
            }
#pragma unroll
            for (int ni = 0; ni < 8; ni++) {
                mma_f16(accO[0][ni][0], accO[0][ni][1], accO[0][ni][2], accO[0][ni][3],
                        pa[0][ks][0], pa[0][ks][1], pa[0][ks][2], pa[0][ks][3],
                        bv[ni][0], bv[ni][1]);
                mma_f16(accO[1][ni][0], accO[1][ni][1], accO[1][ni][2], accO[1][ni][3],
                        pa[1][ks][0], pa[1][ks][1], pa[1][ks][2], pa[1][ks][3],
                        bv[ni][0], bv[ni][1]);
            }
        }
    }

    // ---- epilogue ----
#pragma unroll
    for (int mi = 0; mi < 2; mi++) {
        ls[mi][0] += __shfl_xor_sync(0xffffffffu, ls[mi][0], 1);
        ls[mi][0] += __shfl_xor_sync(0xffffffffu, ls[mi][0], 2);
        ls[mi][1] += __shfl_xor_sync(0xffffffffu, ls[mi][1], 1);
        ls[mi][1] += __shfl_xor_sync(0xffffffffu, ls[mi][1], 2);
    }
    if (md == 0) {
#pragma unroll
        for (int mi = 0; mi < 2; mi++) {
            float inv0 = 1.f / ls[mi][0], inv1 = 1.f / ls[mi][1];
            int row = bn0 + q0 + qrow + mi * 16;
#pragma unroll
            for (int ni = 0; ni < 8; ni++) {
                int col = h * HD + ni * 8 + gc * 2;
                *(uint32_t*)&g_sa[(size_t)row * DIM + col] =
                    pack_h2(accO[mi][ni][1] * inv0, accO[mi][ni][0] * inv0);
                *(uint32_t*)&g_sa[(size_t)(row + 8) * DIM + col] =
                    pack_h2(accO[mi][ni][3] * inv1, accO[mi][ni][2] * inv1);
            }
        }
    } else {
        __half* Po = (md == 1) ? g_o0 : g_o1;
        float*  Pl = (md == 1) ? g_l0 : g_l1;
#pragma unroll
        for (int mi = 0; mi < 2; mi++) {
            int row = bn0 + q0 + qrow + mi * 16;
            if (gc == 0) {
                Pl[(size_t)row * NH + h]       = ls[mi][0];
                Pl[(size_t)(row + 8) * NH + h] = ls[mi][1];
            }
#pragma unroll
            for (int ni = 0; ni < 8; ni++) {
                int col = h * HD + ni * 8 + gc * 2;
                *(uint32_t*)&Po[(size_t)row * DIM + col] =
                    pack_h2(accO[mi][ni][1], accO[mi][ni][0]);
                *(uint32_t*)&Po[(size_t)(row + 8) * DIM + col] =
                    pack_h2(accO[mi][ni][3], accO[mi][ni][2]);
            }
        }
    }
}

// ---------------- split-KV combine (fp16 partials): 1024 blocks x 256 thr ----------
// each thread: 8 halves (uint4) from each partial, h2 add, scale, store uint4.
__global__ void combine_kernel()
{
    const int idx = blockIdx.x * 256 + threadIdx.x;       // 0..262143
    const int b = idx >> 17;                               // 131072 threads per batch
    const int r = idx & 131071;
    const int rl = 1024 + (r >> 7);                        // 128 threads per row
    const int col = (r & 127) * 8;
    const size_t row = (size_t)b * SEQ + rl;
    const int h = col >> 6;
    const float inv = 1.f / (g_l0[row * NH + h] + g_l1[row * NH + h]);
    uint4 a = *(const uint4*)&g_o0[row * DIM + col];
    uint4 c = *(const uint4*)&g_o1[row * DIM + col];
    uint32_t sum[4] = { hadd2u(a.x, c.x), hadd2u(a.y, c.y),
                        hadd2u(a.z, c.z), hadd2u(a.w, c.w) };
    uint4 o;
    uint32_t* op = (uint32_t*)&o;
#pragma unroll
    for (int t = 0; t < 4; t++) {
        float2 f = __half22float2(*(const __half2*)&sum[t]);
        op[t] = pack_h2(f.y * inv, f.x * inv);
    }
    *(uint4*)&g_sa[row * DIM + col] = o;
}

// ---------------- launch ----------------
extern "C" void kernel_launch(void* const* d_in, const int* in_sizes, int n_in,
                              void* d_out, int out_size)
{
    const float* x    = (const float*)d_in[0];
    const float* Wqkv = (const float*)d_in[1];
    const float* bqkv = (const float*)d_in[2];
    const float* Wo   = (const float*)d_in[3];
    const float* bo   = (const float*)d_in[4];
    float* out = (float*)d_out;

    __half *xh, *wqkvT, *woT, *qkv, *sa;
    cudaGetSymbolAddress((void**)&xh,    g_x);
    cudaGetSymbolAddress((void**)&wqkvT, g_wqkvT);
    cudaGetSymbolAddress((void**)&woT,   g_woT);
    cudaGetSymbolAddress((void**)&qkv,   g_qkv);
    cudaGetSymbolAddress((void**)&sa,    g_sa);

    cudaFuncSetAttribute(gemm_h<1>, cudaFuncAttributeMaxDynamicSharedMemorySize, GEMM_SMEM);
    cudaFuncSetAttribute(gemm_h<0>, cudaFuncAttributeMaxDynamicSharedMemorySize, GEMM_SMEM);
    cudaFuncSetAttribute(attn_h, cudaFuncAttributeMaxDynamicSharedMemorySize, ATTN_SMEM);

    prep_kernel<<<4096, 256>>>(x, Wqkv, Wo);
    gemm_h<1><<<dim3(NQKV / 128, BNR / 128), 256, GEMM_SMEM>>>(xh, wqkvT, bqkv, qkv, DIM, NQKV);
    attn_h<<<dim3(24, NH, BB), 128, ATTN_SMEM>>>();
    combine_kernel<<<1024, 256>>>();
    gemm_h<0><<<dim3(DIM / 128, BNR / 128), 256, GEMM_SMEM>>>(sa, woT, bo, out, DIM, DIM);
}

// round 17
// speedup vs baseline: 1.0839x; 1.0042x over previous
#include <cuda_runtime.h>
#include <cuda_fp16.h>
#include <cstdint>

// ---------------- problem constants ----------------
#define BB   2
#define SEQ  2048
#define DIM  1024
#define NH   16
#define HD   64
#define BNR  (BB*SEQ)        // 4096
#define QKVC (3*HD)          // 192
#define NQKV (NH*QKVC)       // 3072

// softmax scale folded into q at gemm1 epilogue: 0.125 * log2(e)
#define QSCALE 0.1803368801111204f

// ---------------- device scratch ----------------
__device__ __half g_x    [BNR * DIM];
__device__ __half g_wqkvT[NQKV * DIM];
__device__ __half g_woT  [DIM * DIM];
__device__ __half g_qkv  [BNR * NQKV];
__device__ __half g_sa   [BNR * DIM];
__device__ __half g_o0   [BNR * DIM];    // split-KV partial O (split 0, fp16)
__device__ __half g_o1   [BNR * DIM];    // split 1
__device__ float  g_l0   [BNR * NH];     // split-KV partial l (fp32)
__device__ float  g_l1   [BNR * NH];

// split-KV schedule: 24 blocks per (b,h), sorted by cost desc.
__constant__ short c_qt[24] = {7,15,15,14,14,6,13,13,12,12,5,11,11,10,10,4,9,9,8,8,3,2,1,0};
__constant__ short c_k0[24] = {0,0,16,0,15,0,0,14,0,13,0,0,12,0,11,0,0,10,0,9,0,0,0,0};
__constant__ short c_k1[24] = {16,16,32,15,30,14,14,28,13,26,12,12,24,11,22,10,10,20,9,18,8,6,4,2};
__constant__ short c_md[24] = {0,1,2,1,2,0,1,2,1,2,0,1,2,1,2,0,1,2,1,2,0,0,0,0};

// ---------------- helpers ----------------
__device__ __forceinline__ uint32_t pack_h2(float hi, float lo) {
    uint32_t d; asm("cvt.rn.f16x2.f32 %0, %1, %2;" : "=r"(d) : "f"(hi), "f"(lo)); return d;
}
__device__ __forceinline__ uint32_t ex2_h2(uint32_t x) {
    uint32_t r; asm("ex2.approx.f16x2 %0, %1;" : "=r"(r) : "r"(x)); return r;
}
__device__ __forceinline__ uint32_t hadd2u(uint32_t a, uint32_t b) {
    uint32_t r; asm("add.f16x2 %0, %1, %2;" : "=r"(r) : "r"(a), "r"(b)); return r;
}
__device__ __forceinline__ uint32_t smem_u32(const void* p) {
    uint32_t a;
    asm("{ .reg .u64 t; cvta.to.shared.u64 t, %1; cvt.u32.u64 %0, t; }" : "=r"(a) : "l"(p));
    return a;
}
#define CP16(dst, src) asm volatile("cp.async.cg.shared.global [%0], [%1], 16;" :: "r"(dst), "l"(src) : "memory")
#define CP_COMMIT()    asm volatile("cp.async.commit_group;" ::: "memory")
#define CP_WAIT1()     asm volatile("cp.async.wait_group 1;" ::: "memory")

__device__ __forceinline__ void mma_f16(float& d0, float& d1, float& d2, float& d3,
                                        uint32_t a0, uint32_t a1, uint32_t a2, uint32_t a3,
                                        uint32_t b0, uint32_t b1)
{
    asm volatile("mma.sync.aligned.m16n8k16.row.col.f32.f16.f16.f32 "
                 "{%0,%1,%2,%3}, {%4,%5,%6,%7}, {%8,%9}, {%0,%1,%2,%3};"
                 : "+f"(d0), "+f"(d1), "+f"(d2), "+f"(d3)
                 : "r"(a0), "r"(a1), "r"(a2), "r"(a3), "r"(b0), "r"(b1));
}
__device__ __forceinline__ void ldsm4(uint32_t& r0, uint32_t& r1, uint32_t& r2, uint32_t& r3,
                                      uint32_t addr)
{
    asm volatile("ldmatrix.sync.aligned.m8n8.x4.shared.b16 {%0,%1,%2,%3}, [%4];"
                 : "=r"(r0), "=r"(r1), "=r"(r2), "=r"(r3) : "r"(addr));
}
__device__ __forceinline__ void ldsm4t(uint32_t& r0, uint32_t& r1, uint32_t& r2, uint32_t& r3,
                                       uint32_t addr)
{
    asm volatile("ldmatrix.sync.aligned.m8n8.x4.trans.shared.b16 {%0,%1,%2,%3}, [%4];"
                 : "=r"(r0), "=r"(r1), "=r"(r2), "=r"(r3) : "r"(addr));
}

// ---------------- fused prep: x->half (2 f4/thr), coalesced transposes -------------
__global__ void prep_kernel(const float* __restrict__ x,
                            const float* __restrict__ Wqkv,
                            const float* __restrict__ Wo)
{
    __shared__ float t[32][65];
    const int b = blockIdx.x, tid = threadIdx.x;

    if (b < 2048) {
        int i = b * 512 + tid;
        float4 v0 = ((const float4*)x)[i];
        float4 v1 = ((const float4*)x)[i + 256];
        uint2 o0 = { pack_h2(v0.y, v0.x), pack_h2(v0.w, v0.z) };
        uint2 o1 = { pack_h2(v1.y, v1.x), pack_h2(v1.w, v1.z) };
        ((uint2*)g_x)[i] = o0;
        ((uint2*)g_x)[i + 256] = o1;
        return;
    }

    const float* inz; __half* outz; int C, bx, by;
    const int R = DIM;
    if (b < 3584) {
        int bb = b - 2048;
        int z = bb / 96, rem = bb % 96;
        int bxi = rem % 6, byi = rem / 6;
        C = QKVC; bx = bxi * 32; by = byi * 64;
        inz = Wqkv + (size_t)z * R * C;
        outz = g_wqkvT + (size_t)z * R * C;
    } else {
        int bb = b - 3584;
        int bxi = bb & 31, byi = bb >> 5;
        C = DIM; bx = bxi * 32; by = byi * 64;
        inz = Wo; outz = g_woT;
    }
    const int tx = tid & 31, ty = tid >> 5;
#pragma unroll
    for (int j = 0; j < 8; j++) {
        int lr = ty + j * 8;
        t[tx][lr] = inz[(size_t)(by + lr) * C + bx + tx];
    }
    __syncthreads();
#pragma unroll
    for (int i = ty; i < 32; i += 8) {
        uint32_t v = pack_h2(t[i][2 * tx + 1], t[i][2 * tx]);
        *(uint32_t*)&outz[(size_t)(bx + i) * R + by + 2 * tx] = v;
    }
}

// ================= fp16 mma GEMM: 4 warps, 64x64 warp tile, 3-stage cp.async ========
// Block 128x128, 128 threads. Per k16: 8 LDSM + 32 HMMA per warp (HMMA-heavy issue mix).
#define GEMM_SMEM (3 * 32768)

template<int MODE>   // 0: float out; 1: half out with q-scale (qkv)
__global__ __launch_bounds__(128, 2)
void gemm_h(const __half* __restrict__ A, const __half* __restrict__ Bt,
            const float* __restrict__ bias, void* __restrict__ Cv, int K, int N)
{
    extern __shared__ char smc[];
    const int tid = threadIdx.x, lane = tid & 31, wid = tid >> 5;
    const int warpM = (wid & 1) * 64, warpN = (wid >> 1) * 64;
    const int m0 = blockIdx.y * 128, n0 = blockIdx.x * 128;
    const int gr = lane >> 2, gc = lane & 3;
    const uint32_t sbase = smem_u32(smc);

    // cp.async: 2048 granules/stage, 128 threads -> 16 CP16 each (8 A + 8 B)
    const int crow = tid >> 3, cg = tid & 7;                   // 16 rows x 8 granules
    const uint32_t cdst = (uint32_t)(crow * 128 + ((cg ^ (crow & 7)) << 4));
    const __half* Asrc = A + (size_t)(m0 + crow) * K + cg * 8;
    const __half* Bsrc = Bt + (size_t)(n0 + crow) * K + cg * 8;

    // LDSM per-lane
    const int a_r = warpM + (lane & 15);
    const uint32_t aX = (uint32_t)(a_r & 7), agsel = (uint32_t)(lane >> 4);
    const int b_r = warpN + ((lane >> 4) << 3) + (lane & 7);
    const uint32_t bX = (uint32_t)(lane & 7), bgsel = (uint32_t)((lane >> 3) & 1);

    float acc[4][8][4];
#pragma unroll
    for (int mi = 0; mi < 4; mi++)
#pragma unroll
        for (int ni = 0; ni < 8; ni++)
#pragma unroll
            for (int q = 0; q < 4; q++) acc[mi][ni][q] = 0.f;

    const int NC = K / 64;

    auto issue = [&](int c, int st) {
        const uint32_t stb = sbase + (uint32_t)(st * 32768);
        const __half* Ap = Asrc + c * 64;
        const __half* Bp = Bsrc + c * 64;
#pragma unroll
        for (int t = 0; t < 8; t++) {
            CP16(stb + cdst + (uint32_t)(t * 2048), Ap + (size_t)t * 16 * K);
            CP16(stb + 16384u + cdst + (uint32_t)(t * 2048), Bp + (size_t)t * 16 * K);
        }
    };

    issue(0, 0); CP_COMMIT();
    issue(1, 1); CP_COMMIT();

    for (int c = 0; c < NC; c++) {
        const int st = c % 3;
        CP_WAIT1();
        __syncthreads();
        if (c + 2 < NC) issue(c + 2, (c + 2) % 3);
        CP_COMMIT();

        const uint32_t stb = sbase + (uint32_t)(st * 32768);
        const uint32_t aBase = stb + (uint32_t)(a_r * 128);
        const uint32_t bBase = stb + 16384u + (uint32_t)(b_r * 128);
#pragma unroll
        for (int ks = 0; ks < 4; ks++) {
            const uint32_t ac = ((2u * ks + agsel) ^ aX) << 4;
            const uint32_t bc = ((2u * ks + bgsel) ^ bX) << 4;
            uint32_t a[4][4], b[8][2];
#pragma unroll
            for (int mt = 0; mt < 4; mt++)
                ldsm4(a[mt][0], a[mt][1], a[mt][2], a[mt][3],
                      aBase + (uint32_t)(mt * 2048) + ac);
#pragma unroll
            for (int p = 0; p < 4; p++)
                ldsm4(b[2*p][0], b[2*p][1], b[2*p+1][0], b[2*p+1][1],
                      bBase + (uint32_t)(p * 2048) + bc);
#pragma unroll
            for (int mi = 0; mi < 4; mi++)
#pragma unroll
                for (int ni = 0; ni < 8; ni++)
                    mma_f16(acc[mi][ni][0], acc[mi][ni][1], acc[mi][ni][2], acc[mi][ni][3],
                            a[mi][0], a[mi][1], a[mi][2], a[mi][3], b[ni][0], b[ni][1]);
        }
    }

#pragma unroll
    for (int mi = 0; mi < 4; mi++) {
        int row = m0 + warpM + mi * 16 + gr;
#pragma unroll
        for (int ni = 0; ni < 8; ni++) {
            int col = n0 + warpN + ni * 8 + gc * 2;
            float2 bsv = *(const float2*)(bias + col);
            float v00 = acc[mi][ni][0] + bsv.x, v01 = acc[mi][ni][1] + bsv.y;
            float v10 = acc[mi][ni][2] + bsv.x, v11 = acc[mi][ni][3] + bsv.y;
            if (MODE == 1) {
                int j = col % QKVC;
                float sc = (j >= 64 && j < 128) ? QSCALE : 1.0f;
                v00 *= sc; v01 *= sc; v10 *= sc; v11 *= sc;
                __half* Ch = (__half*)Cv;
                *(uint32_t*)&Ch[(size_t)row * N + col]       = pack_h2(v01, v00);
                *(uint32_t*)&Ch[(size_t)(row + 8) * N + col] = pack_h2(v11, v10);
            } else {
                float* Cf = (float*)Cv;
                float2 w0 = { v00, v01 }, w1 = { v10, v11 };
                *(float2*)&Cf[(size_t)row * N + col] = w0;
                *(float2*)&Cf[(size_t)(row + 8) * N + col] = w1;
            }
        }
    }
}

// ================= fp16 flash attention: split-KV (fp16 partials), h2 exp ==========
#define ATTN_SMEM 65536

__global__ __launch_bounds__(128, 3)
void attn_h()
{
    extern __shared__ char smc[];
    const int tid = threadIdx.x, lane = tid & 31, wid = tid >> 5;
    const int idx = blockIdx.x;
    const int qt = c_qt[idx], kt0 = c_k0[idx], kt1 = c_k1[idx], md = c_md[idx];
    const int h = blockIdx.y, b = blockIdx.z;
    const int bn0 = b * SEQ;
    const int colK = h * QKVC, colQ = colK + HD, colV = colK + 2 * HD;
    const int q0 = qt * 128;
    const int gr = lane >> 2, gc = lane & 3;
    const int qrow = wid * 32 + gr;

    const uint32_t sbase = smem_u32(smc);
    const uint32_t uQ = sbase;
    const uint32_t uKV = sbase + 16384u;

    const int crow = tid >> 3, cg = tid & 7;
    const uint32_t cdst = (uint32_t)(crow * 128 + ((cg ^ (crow & 7)) << 4));

    auto issue_kv = [&](int kt, int st) {
        const __half* Kp = g_qkv + (size_t)(bn0 + kt * 64 + crow) * NQKV + colK + cg * 8;
        const __half* Vp = g_qkv + (size_t)(bn0 + kt * 64 + crow) * NQKV + colV + cg * 8;
        const uint32_t stb = uKV + (uint32_t)(st * 16384);
#pragma unroll
        for (int t = 0; t < 4; t++) {
            CP16(stb + cdst + (uint32_t)(t * 2048), Kp + (size_t)t * 16 * NQKV);
            CP16(stb + 8192u + cdst + (uint32_t)(t * 2048), Vp + (size_t)t * 16 * NQKV);
        }
    };

    {
        const __half* Qp = g_qkv + (size_t)(bn0 + q0 + crow) * NQKV + colQ + cg * 8;
#pragma unroll
        for (int t = 0; t < 8; t++)
            CP16(uQ + cdst + (uint32_t)(t * 2048), Qp + (size_t)t * 16 * NQKV);
    }
    issue_kv(kt0, 0); CP_COMMIT();
    issue_kv(kt0 + 1, 1); CP_COMMIT();

    const int qa_r = wid * 32 + (lane & 15);
    const uint32_t qX = (uint32_t)(qa_r & 7), agsel = (uint32_t)(lane >> 4);
    const uint32_t qBase = uQ + (uint32_t)(qa_r * 128);
    const int kb_r = ((lane >> 4) << 3) + (lane & 7);
    const uint32_t kX = (uint32_t)(lane & 7), bgsel = (uint32_t)((lane >> 3) & 1);
    const int v_r = (((lane >> 3) & 1) << 3) + (lane & 7);
    const uint32_t vX = (uint32_t)(lane & 7), vgsel = (uint32_t)(lane >> 4);

    float accO[2][8][4];
#pragma unroll
    for (int mi = 0; mi < 2; mi++)
#pragma unroll
        for (int ni = 0; ni < 8; ni++)
#pragma unroll
            for (int q = 0; q < 4; q++) accO[mi][ni][q] = 0.f;
    float ls[2][2] = { {0.f, 0.f}, {0.f, 0.f} };

    const int lastq = q0 + wid * 32 + 31;

    for (int kt = kt0; kt < kt1; kt++) {
        const int st = (kt - kt0) % 3;
        CP_WAIT1();
        __syncthreads();
        if (kt + 2 < kt1) issue_kv(kt + 2, (kt - kt0 + 2) % 3);
        CP_COMMIT();

        if (kt * 64 > lastq) continue;

        const uint32_t stK = uKV + (uint32_t)(st * 16384);
        const uint32_t stV = stK + 8192u;

        // ---- S = Q @ K^T ----
        float s[2][8][4];
#pragma unroll
        for (int mi = 0; mi < 2; mi++)
#pragma unroll
            for (int ni = 0; ni < 8; ni++)
#pragma unroll
                for (int q = 0; q < 4; q++) s[mi][ni][q] = 0.f;
#pragma unroll
        for (int ks = 0; ks < 4; ks++) {
            const uint32_t ac = ((2u * ks + agsel) ^ qX) << 4;
            const uint32_t bc = ((2u * ks + bgsel) ^ kX) << 4;
            uint32_t a[2][4], bk[8][2];
            ldsm4(a[0][0], a[0][1], a[0][2], a[0][3], qBase + ac);
            ldsm4(a[1][0], a[1][1], a[1][2], a[1][3], qBase + 2048u + ac);
#pragma unroll
            for (int p = 0; p < 4; p++)
                ldsm4(bk[2*p][0], bk[2*p][1], bk[2*p+1][0], bk[2*p+1][1],
                      stK + (uint32_t)((kb_r + p * 16) * 128) + bc);
#pragma unroll
            for (int ni = 0; ni < 8; ni++) {
                mma_f16(s[0][ni][0], s[0][ni][1], s[0][ni][2], s[0][ni][3],
                        a[0][0], a[0][1], a[0][2], a[0][3], bk[ni][0], bk[ni][1]);
                mma_f16(s[1][ni][0], s[1][ni][1], s[1][ni][2], s[1][ni][3],
                        a[1][0], a[1][1], a[1][2], a[1][3], bk[ni][0], bk[ni][1]);
            }
        }

        // ---- causal mask ----
        if (kt >= 2 * qt) {
            const int kb = kt * 64;
#pragma unroll
            for (int mi = 0; mi < 2; mi++) {
                const int qg = q0 + qrow + mi * 16;
#pragma unroll
                for (int ni = 0; ni < 8; ni++) {
                    int kc = kb + ni * 8 + gc * 2;
                    if (kc     > qg    ) s[mi][ni][0] = -1e30f;
                    if (kc + 1 > qg    ) s[mi][ni][1] = -1e30f;
                    if (kc     > qg + 8) s[mi][ni][2] = -1e30f;
                    if (kc + 1 > qg + 8) s[mi][ni][3] = -1e30f;
                }
            }
        }

        // ---- pack s to h2, then P = ex2.f16x2 ----
        uint32_t pa[2][4][4];
#pragma unroll
        for (int mi = 0; mi < 2; mi++)
#pragma unroll
            for (int ks = 0; ks < 4; ks++) {
                pa[mi][ks][0] = ex2_h2(pack_h2(s[mi][2*ks][1],   s[mi][2*ks][0]));
                pa[mi][ks][1] = ex2_h2(pack_h2(s[mi][2*ks][3],   s[mi][2*ks][2]));
                pa[mi][ks][2] = ex2_h2(pack_h2(s[mi][2*ks+1][1], s[mi][2*ks+1][0]));
                pa[mi][ks][3] = ex2_h2(pack_h2(s[mi][2*ks+1][3], s[mi][2*ks+1][2]));
            }

        // ---- tile-local row sums in h2, folded into fp32 ----
#pragma unroll
        for (int mi = 0; mi < 2; mi++) {
            uint32_t h0 = hadd2u(hadd2u(pa[mi][0][0], pa[mi][0][2]),
                                 hadd2u(pa[mi][1][0], pa[mi][1][2]));
            uint32_t h0b = hadd2u(hadd2u(pa[mi][2][0], pa[mi][2][2]),
                                  hadd2u(pa[mi][3][0], pa[mi][3][2]));
            uint32_t h1 = hadd2u(hadd2u(pa[mi][0][1], pa[mi][0][3]),
                                 hadd2u(pa[mi][1][1], pa[mi][1][3]));
            uint32_t h1b = hadd2u(hadd2u(pa[mi][2][1], pa[mi][2][3]),
                                  hadd2u(pa[mi][3][1], pa[mi][3][3]));
            float2 f0 = __half22float2(*(const __half2*)&h0);
            float2 f0b = __half22float2(*(const __half2*)&h0b);
            float2 f1 = __half22float2(*(const __half2*)&h1);
            float2 f1b = __half22float2(*(const __half2*)&h1b);
            ls[mi][0] += (f0.x + f0.y) + (f0b.x + f0b.y);
            ls[mi][1] += (f1.x + f1.y) + (f1b.x + f1b.y);
        }

        // ---- O += P @ V ----
#pragma unroll
        for (int ks = 0; ks < 4; ks++) {
            uint32_t bv[8][2];
#pragma unroll
            for (int p = 0; p < 4; p++) {
                const uint32_t vc = ((2u * p + vgsel) ^ vX) << 4;
                ldsm4t(bv[2*p][0], bv[2*p][1], bv[2*p+1][0], bv[2*p+1][1],
                       stV + (uint32_t)((v_r + ks * 16) * 128) + vc);
            }
#pragma unroll
            for (int ni = 0; ni < 8; ni++) {
                mma_f16(accO[0][ni][0], accO[0][ni][1], accO[0][ni][2], accO[0][ni][3],
                        pa[0][ks][0], pa[0][ks][1], pa[0][ks][2], pa[0][ks][3],
                        bv[ni][0], bv[ni][1]);
                mma_f16(accO[1][ni][0], accO[1][ni][1], accO[1][ni][2], accO[1][ni][3],
                        pa[1][ks][0], pa[1][ks][1], pa[1][ks][2], pa[1][ks][3],
                        bv[ni][0], bv[ni][1]);
            }
        }
    }

    // ---- epilogue ----
#pragma unroll
    for (int mi = 0; mi < 2; mi++) {
        ls[mi][0] += __shfl_xor_sync(0xffffffffu, ls[mi][0], 1);
        ls[mi][0] += __shfl_xor_sync(0xffffffffu, ls[mi][0], 2);
        ls[mi][1] += __shfl_xor_sync(0xffffffffu, ls[mi][1], 1);
        ls[mi][1] += __shfl_xor_sync(0xffffffffu, ls[mi][1], 2);
    }
    if (md == 0) {
#pragma unroll
        for (int mi = 0; mi < 2; mi++) {
            float inv0 = 1.f / ls[mi][0], inv1 = 1.f / ls[mi][1];
            int row = bn0 + q0 + qrow + mi * 16;
#pragma unroll
            for (int ni = 0; ni < 8; ni++) {
                int col = h * HD + ni * 8 + gc * 2;
                *(uint32_t*)&g_sa[(size_t)row * DIM + col] =
                    pack_h2(accO[mi][ni][1] * inv0, accO[mi][ni][0] * inv0);
                *(uint32_t*)&g_sa[(size_t)(row + 8) * DIM + col] =
                    pack_h2(accO[mi][ni][3] * inv1, accO[mi][ni][2] * inv1);
            }
        }
    } else {
        __half* Po = (md == 1) ? g_o0 : g_o1;
        float*  Pl = (md == 1) ? g_l0 : g_l1;
#pragma unroll
        for (int mi = 0; mi < 2; mi++) {
            int row = bn0 + q0 + qrow + mi * 16;
            if (gc == 0) {
                Pl[(size_t)row * NH + h]       = ls[mi][0];
                Pl[(size_t)(row + 8) * NH + h] = ls[mi][1];
            }
#pragma unroll
            for (int ni = 0; ni < 8; ni++) {
                int col = h * HD + ni * 8 + gc * 2;
                *(uint32_t*)&Po[(size_t)row * DIM + col] =
                    pack_h2(accO[mi][ni][1], accO[mi][ni][0]);
                *(uint32_t*)&Po[(size_t)(row + 8) * DIM + col] =
                    pack_h2(accO[mi][ni][3], accO[mi][ni][2]);
            }
        }
    }
}

// ---------------- split-KV combine (fp16 partials): 1024 blocks x 256 thr ----------
__global__ void combine_kernel()
{
    const int idx = blockIdx.x * 256 + threadIdx.x;
    const int b = idx >> 17;
    const int r = idx & 131071;
    const int rl = 1024 + (r >> 7);
    const int col = (r & 127) * 8;
    const size_t row = (size_t)b * SEQ + rl;
    const int h = col >> 6;
    const float inv = 1.f / (g_l0[row * NH + h] + g_l1[row * NH + h]);
    uint4 a = *(const uint4*)&g_o0[row * DIM + col];
    uint4 c = *(const uint4*)&g_o1[row * DIM + col];
    uint32_t sum[4] = { hadd2u(a.x, c.x), hadd2u(a.y, c.y),
                        hadd2u(a.z, c.z), hadd2u(a.w, c.w) };
    uint4 o;
    uint32_t* op = (uint32_t*)&o;
#pragma unroll
    for (int t = 0; t < 4; t++) {
        float2 f = __half22float2(*(const __half2*)&sum[t]);
        op[t] = pack_h2(f.y * inv, f.x * inv);
    }
    *(uint4*)&g_sa[row * DIM + col] = o;
}

// ---------------- launch ----------------
extern "C" void kernel_launch(void* const* d_in, const int* in_sizes, int n_in,
                              void* d_out, int out_size)
{
    const float* x    = (const float*)d_in[0];
    const float* Wqkv = (const float*)d_in[1];
    const float* bqkv = (const float*)d_in[2];
    const float* Wo   = (const float*)d_in[3];
    const float* bo   = (const float*)d_in[4];
    float* out = (float*)d_out;

    __half *xh, *wqkvT, *woT, *qkv, *sa;
    cudaGetSymbolAddress((void**)&xh,    g_x);
    cudaGetSymbolAddress((void**)&wqkvT, g_wqkvT);
    cudaGetSymbolAddress((void**)&woT,   g_woT);
    cudaGetSymbolAddress((void**)&qkv,   g_qkv);
    cudaGetSymbolAddress((void**)&sa,    g_sa);

    cudaFuncSetAttribute(gemm_h<1>, cudaFuncAttributeMaxDynamicSharedMemorySize, GEMM_SMEM);
    cudaFuncSetAttribute(gemm_h<0>, cudaFuncAttributeMaxDynamicSharedMemorySize, GEMM_SMEM);
    cudaFuncSetAttribute(attn_h, cudaFuncAttributeMaxDynamicSharedMemorySize, ATTN_SMEM);

    prep_kernel<<<4096, 256>>>(x, Wqkv, Wo);
    gemm_h<1><<<dim3(NQKV / 128, BNR / 128), 128, GEMM_SMEM>>>(xh, wqkvT, bqkv, qkv, DIM, NQKV);
    attn_h<<<dim3(24, NH, BB), 128, ATTN_SMEM>>>();
    combine_kernel<<<1024, 256>>>();
    gemm_h<0><<<dim3(DIM / 128, BNR / 128), 128, GEMM_SMEM>>>(sa, woT, bo, out, DIM, DIM);
}